// round 1
// baseline (speedup 1.0000x reference)
#include <cuda_runtime.h>

#define NROWS 8192
#define H 1024

// ---------------- scratch (__device__ globals; no allocation allowed) ----------------
__device__ float g_G[H * H];      // x^T x
__device__ float g_T[H * H];      // Wk @ G
__device__ float g_M[H * H];      // k^T v
__device__ float g_P[H * H];      // Wq^T M / 32
__device__ float g_spart[32 * H]; // partial reductions (reused)
__device__ float g_s[H];          // column sums of x
__device__ float g_ks[H];         // Wk @ s
__device__ float g_vs[H];         // Wv @ s
__device__ float g_c[H];          // bq^T M / 32

// ---------------- column sums of x (split over rows, then reduce) ----------------
__global__ void colsum_part(const float* __restrict__ x, float* __restrict__ part) {
    int j = blockIdx.x * 256 + threadIdx.x;   // grid.x = 4
    int nb = blockIdx.y;                      // grid.y = 32
    float s = 0.f;
    int n0 = nb * (NROWS / 32);
    for (int n = n0; n < n0 + (NROWS / 32); n++) s += x[n * H + j];
    part[nb * H + j] = s;
}

__global__ void reduce_part(const float* __restrict__ part, float* __restrict__ out,
                            int cnt, float scale) {
    int j = blockIdx.x * 256 + threadIdx.x;   // grid.x = 4
    float s = 0.f;
    for (int i = 0; i < cnt; i++) s += part[i * H + j];
    out[j] = s * scale;
}

// ---------------- G = x^T x : [1024,1024], K = 8192 ----------------
// 64x64 tile per CTA, 256 threads, 4x4 micro-tile, K-tile 16. Grid 16x16 = 256 CTAs.
__global__ void ata_kernel(const float* __restrict__ x, float* __restrict__ G) {
    __shared__ float Xa[16][68];
    __shared__ float Xb[16][68];
    const int i0 = blockIdx.y * 64, j0 = blockIdx.x * 64;
    const int tid = threadIdx.x;
    const int tx = tid & 15, ty = tid >> 4;
    float acc[4][4] = {};
    const int r = tid >> 4;          // 0..15 (k-row within tile)
    const int c = (tid & 15) * 4;    // 0..60 (col within tile)
    for (int n0 = 0; n0 < NROWS; n0 += 16) {
        float4 va = *(const float4*)(x + (n0 + r) * H + i0 + c);
        float4 vb = *(const float4*)(x + (n0 + r) * H + j0 + c);
        Xa[r][c + 0] = va.x; Xa[r][c + 1] = va.y; Xa[r][c + 2] = va.z; Xa[r][c + 3] = va.w;
        Xb[r][c + 0] = vb.x; Xb[r][c + 1] = vb.y; Xb[r][c + 2] = vb.z; Xb[r][c + 3] = vb.w;
        __syncthreads();
        #pragma unroll
        for (int kk = 0; kk < 16; kk++) {
            float a[4], b[4];
            #pragma unroll
            for (int i = 0; i < 4; i++) a[i] = Xa[kk][ty * 4 + i];
            #pragma unroll
            for (int j = 0; j < 4; j++) b[j] = Xb[kk][tx * 4 + j];
            #pragma unroll
            for (int i = 0; i < 4; i++)
                #pragma unroll
                for (int j = 0; j < 4; j++)
                    acc[i][j] += a[i] * b[j];
        }
        __syncthreads();
    }
    #pragma unroll
    for (int i = 0; i < 4; i++) {
        int m = i0 + ty * 4 + i;
        #pragma unroll
        for (int j = 0; j < 4; j++)
            G[m * H + j0 + tx * 4 + j] = acc[i][j];
    }
}

// ---------------- generic 1024^3 fp32 GEMM: C = alpha * op(A) @ op(B) ----------------
// TA/TB: 0 = no transpose, 1 = transpose. All matrices [1024,1024] row-major.
template <int TA, int TB>
__global__ void gemm1k(const float* __restrict__ A, const float* __restrict__ B,
                       float* __restrict__ C, float alpha) {
    __shared__ float As[16][68];
    __shared__ float Bs[16][68];
    const int m0 = blockIdx.y * 64, n0 = blockIdx.x * 64;
    const int tid = threadIdx.x;
    const int tx = tid & 15, ty = tid >> 4;
    float acc[4][4] = {};
    for (int k0 = 0; k0 < H; k0 += 16) {
        if (TA == 0) {  // op(A)[m][k] = A[m][k]
            int kc = tid & 15, mrb = tid >> 4;
            #pragma unroll
            for (int p = 0; p < 4; p++) {
                int mr = mrb + p * 16;
                As[kc][mr] = A[(m0 + mr) * H + k0 + kc];
            }
        } else {        // op(A)[m][k] = A[k][m]
            int mc = tid & 63, krb = tid >> 6;
            #pragma unroll
            for (int p = 0; p < 4; p++) {
                int kr = krb + p * 4;
                As[kr][mc] = A[(k0 + kr) * H + m0 + mc];
            }
        }
        if (TB == 0) {  // op(B)[k][n] = B[k][n]
            int nc = tid & 63, krb = tid >> 6;
            #pragma unroll
            for (int p = 0; p < 4; p++) {
                int kr = krb + p * 4;
                Bs[kr][nc] = B[(k0 + kr) * H + n0 + nc];
            }
        } else {        // op(B)[k][n] = B[n][k]
            int kc = tid & 15, nrb = tid >> 4;
            #pragma unroll
            for (int p = 0; p < 4; p++) {
                int nr = nrb + p * 16;
                Bs[kc][nr] = B[(n0 + nr) * H + k0 + kc];
            }
        }
        __syncthreads();
        #pragma unroll
        for (int kk = 0; kk < 16; kk++) {
            float a[4], b[4];
            #pragma unroll
            for (int i = 0; i < 4; i++) a[i] = As[kk][ty * 4 + i];
            #pragma unroll
            for (int j = 0; j < 4; j++) b[j] = Bs[kk][tx * 4 + j];
            #pragma unroll
            for (int i = 0; i < 4; i++)
                #pragma unroll
                for (int j = 0; j < 4; j++)
                    acc[i][j] += a[i] * b[j];
        }
        __syncthreads();
    }
    #pragma unroll
    for (int i = 0; i < 4; i++) {
        int m = m0 + ty * 4 + i;
        #pragma unroll
        for (int j = 0; j < 4; j++)
            C[m * H + n0 + tx * 4 + j] = alpha * acc[i][j];
    }
}

// ---------------- matvec: out = W @ v  (one warp per row) ----------------
__global__ void matvec_k(const float* __restrict__ W, const float* __restrict__ v,
                         float* __restrict__ out) {
    int row = blockIdx.x * 8 + (threadIdx.x >> 5);  // grid 128 x 256 threads
    int lane = threadIdx.x & 31;
    float s = 0.f;
    for (int k = lane; k < H; k += 32) s += W[row * H + k] * v[k];
    #pragma unroll
    for (int o = 16; o > 0; o >>= 1) s += __shfl_xor_sync(0xffffffffu, s, o);
    if (lane == 0) out[row] = s;
}

// ---------------- rank-1 corrections: M += ks bv^T + bk vs^T + N bk bv^T ----------------
__global__ void rank1_k(float* __restrict__ M, const float* __restrict__ ks,
                        const float* __restrict__ bk, const float* __restrict__ vs,
                        const float* __restrict__ bv) {
    int idx = blockIdx.x * 256 + threadIdx.x;   // grid 4096
    int i = idx >> 10, j = idx & 1023;
    M[idx] += ks[i] * bv[j] + bk[i] * (vs[j] + 8192.0f * bv[j]);
}

// ---------------- partial of c_j = sum_i M[i][j] * bq[i] ----------------
__global__ void cvec_part(const float* __restrict__ M, const float* __restrict__ b,
                          float* __restrict__ part) {
    int j = blockIdx.x * 256 + threadIdx.x;  // grid.x = 4
    int ib = blockIdx.y;                     // grid.y = 16
    float s = 0.f;
    for (int i = ib * 64; i < ib * 64 + 64; i++) s += M[i * H + j] * b[i];
    part[ib * H + j] = s;
}

// ---------------- out = x @ P + 1 c^T : [8192,1024] ----------------
// 128x128 tile, 256 threads, 8x8 micro-tile, K-tile 16. Grid (8, 64) = 512 CTAs.
__global__ void xp_kernel(const float* __restrict__ x, const float* __restrict__ P,
                          const float* __restrict__ cb, float* __restrict__ out) {
    __shared__ float As[16][128];
    __shared__ float Bs[16][132];
    const int m0 = blockIdx.y * 128, n0 = blockIdx.x * 128;
    const int tid = threadIdx.x;
    const int tx = tid & 15, ty = tid >> 4;
    float acc[8][8] = {};
    for (int k0 = 0; k0 < H; k0 += 16) {
        // A tile: x[m0+mr][k0+kc], stored transposed As[k][m]
        int mr = tid >> 1;
        #pragma unroll
        for (int p = 0; p < 2; p++) {
            int kc = (tid & 1) * 4 + p * 8;
            float4 va = *(const float4*)(x + (m0 + mr) * H + k0 + kc);
            As[kc + 0][mr] = va.x; As[kc + 1][mr] = va.y;
            As[kc + 2][mr] = va.z; As[kc + 3][mr] = va.w;
        }
        // B tile: P[k0+kr][n0+nc]
        int nc = (tid & 31) * 4;
        #pragma unroll
        for (int p = 0; p < 2; p++) {
            int kr = (tid >> 5) + p * 8;
            float4 vb = *(const float4*)(P + (k0 + kr) * H + n0 + nc);
            *(float4*)&Bs[kr][nc] = vb;
        }
        __syncthreads();
        #pragma unroll
        for (int kk = 0; kk < 16; kk++) {
            float a[8], b[8];
            #pragma unroll
            for (int i = 0; i < 8; i++) a[i] = As[kk][ty * 8 + i];
            #pragma unroll
            for (int j = 0; j < 8; j++) b[j] = Bs[kk][tx * 8 + j];
            #pragma unroll
            for (int i = 0; i < 8; i++)
                #pragma unroll
                for (int j = 0; j < 8; j++)
                    acc[i][j] += a[i] * b[j];
        }
        __syncthreads();
    }
    #pragma unroll
    for (int i = 0; i < 8; i++) {
        int m = m0 + ty * 8 + i;
        #pragma unroll
        for (int j = 0; j < 8; j++)
            out[m * H + n0 + tx * 8 + j] = acc[i][j] + cb[n0 + tx * 8 + j];
    }
}

// ---------------- launch ----------------
extern "C" void kernel_launch(void* const* d_in, const int* in_sizes, int n_in,
                              void* d_out, int out_size) {
    const float* x  = (const float*)d_in[0];
    const float* Wq = (const float*)d_in[1];
    const float* bq = (const float*)d_in[2];
    const float* Wk = (const float*)d_in[3];
    const float* bk = (const float*)d_in[4];
    const float* Wv = (const float*)d_in[5];
    const float* bv = (const float*)d_in[6];
    float* out = (float*)d_out;

    float *G, *T, *M, *P, *spart, *s, *ks, *vs, *c;
    cudaGetSymbolAddress((void**)&G, g_G);
    cudaGetSymbolAddress((void**)&T, g_T);
    cudaGetSymbolAddress((void**)&M, g_M);
    cudaGetSymbolAddress((void**)&P, g_P);
    cudaGetSymbolAddress((void**)&spart, g_spart);
    cudaGetSymbolAddress((void**)&s, g_s);
    cudaGetSymbolAddress((void**)&ks, g_ks);
    cudaGetSymbolAddress((void**)&vs, g_vs);
    cudaGetSymbolAddress((void**)&c, g_c);

    const float inv_sqrt_h = 0.03125f;  // 1/sqrt(1024)

    // s = column sums of x
    colsum_part<<<dim3(4, 32), 256>>>(x, spart);
    reduce_part<<<4, 256>>>(spart, s, 32, 1.0f);

    // G = x^T x   (the only K=8192 rank update)
    ata_kernel<<<dim3(16, 16), 256>>>(x, G);

    // ks = Wk s ; vs = Wv s
    matvec_k<<<128, 256>>>(Wk, s, ks);
    matvec_k<<<128, 256>>>(Wv, s, vs);

    // M = Wk G Wv^T + ks bv^T + bk vs^T + N bk bv^T
    gemm1k<0, 0><<<dim3(16, 16), 256>>>(Wk, G, T, 1.0f);
    gemm1k<0, 1><<<dim3(16, 16), 256>>>(T, Wv, M, 1.0f);
    rank1_k<<<4096, 256>>>(M, ks, bk, vs, bv);

    // P = Wq^T M / sqrt(H)
    gemm1k<1, 0><<<dim3(16, 16), 256>>>(Wq, M, P, inv_sqrt_h);

    // c = M^T bq / sqrt(H)
    cvec_part<<<dim3(4, 16), 256>>>(M, bq, spart);
    reduce_part<<<4, 256>>>(spart, c, 16, inv_sqrt_h);

    // out = x P + 1 c^T
    xp_kernel<<<dim3(8, 64), 256>>>(x, P, c, out);
}

// round 7
// speedup vs baseline: 1.5126x; 1.5126x over previous
#include <cuda_runtime.h>
#include <cuda_bf16.h>
#include <cstdint>
#include <cstddef>

#define NROWS 8192
#define H 1024

// ======================= helpers =======================
__device__ __forceinline__ uint32_t smem_to_u32(const void* p) {
    uint32_t a;
    asm("{ .reg .u64 t; cvta.to.shared.u64 t, %1; cvt.u32.u64 %0, t; }" : "=r"(a) : "l"(p));
    return a;
}
__device__ __forceinline__ void ldmatrix_x4(uint32_t* r, uint32_t addr) {
    asm volatile("ldmatrix.sync.aligned.m8n8.x4.shared.b16 {%0,%1,%2,%3}, [%4];"
                 : "=r"(r[0]), "=r"(r[1]), "=r"(r[2]), "=r"(r[3]) : "r"(addr));
}
__device__ __forceinline__ void mma_16816(float* d, const uint32_t* a, uint32_t b0, uint32_t b1) {
    asm volatile(
        "mma.sync.aligned.m16n8k16.row.col.f32.bf16.bf16.f32 "
        "{%0,%1,%2,%3}, {%4,%5,%6,%7}, {%8,%9}, {%0,%1,%2,%3};"
        : "+f"(d[0]), "+f"(d[1]), "+f"(d[2]), "+f"(d[3])
        : "r"(a[0]), "r"(a[1]), "r"(a[2]), "r"(a[3]), "r"(b0), "r"(b1));
}
__device__ __forceinline__ void cp_async16(uint32_t saddr, const void* gaddr) {
    asm volatile("cp.async.cg.shared.global [%0], [%1], 16;" :: "r"(saddr), "l"(gaddr));
}

// ======================= scratch (device globals only) =======================
__device__ __align__(256) float g_G[H * H];
__device__ __align__(256) float g_T[H * H];
__device__ __align__(256) float g_M[H * H];
__device__ __align__(256) float g_P[H * H];
__device__ __align__(256) float g_cpart[6 * H * H];   // split-K partials
__device__ __align__(256) float g_spart[32 * H];
__device__ float g_s[H];
__device__ float g_ks[H];
__device__ float g_vs[H];
__device__ float g_c[H];

__device__ __align__(256) __nv_bfloat16 g_xt_hi[H * NROWS];
__device__ __align__(256) __nv_bfloat16 g_xt_lo[H * NROWS];
__device__ __align__(256) __nv_bfloat16 g_x_hi[NROWS * H];
__device__ __align__(256) __nv_bfloat16 g_x_lo[NROWS * H];
__device__ __align__(256) __nv_bfloat16 g_wk_hi[H * H], g_wk_lo[H * H];
__device__ __align__(256) __nv_bfloat16 g_wv_hi[H * H], g_wv_lo[H * H];
__device__ __align__(256) __nv_bfloat16 g_wqt_hi[H * H], g_wqt_lo[H * H];
__device__ __align__(256) __nv_bfloat16 g_g_hi[H * H],  g_g_lo[H * H];
__device__ __align__(256) __nv_bfloat16 g_t_hi[H * H],  g_t_lo[H * H];
__device__ __align__(256) __nv_bfloat16 g_mt_hi[H * H], g_mt_lo[H * H];
__device__ __align__(256) __nv_bfloat16 g_pt_hi[H * H], g_pt_lo[H * H];

// ======================= HMMA GEMM: C = alpha * A @ B^T (+ addvec) =======================
// A: [M][Ktot] K-major via 3 segment pointers (hi/lo split terms), row stride lda.
// B: [N][Ktot] K-major via 3 segment pointers, row stride ldb.
// 128x128 CTA tile, 8 warps (2m x 4n), 64x32 warp tile, K-chunk 64, cp.async double buffer.
// gridDim.z = Z split-K slices; Z>1 writes raw partials to C + z*partStride.
struct GemmArgs {
    const __nv_bfloat16* A0; const __nv_bfloat16* A1; const __nv_bfloat16* A2;
    const __nv_bfloat16* B0; const __nv_bfloat16* B1; const __nv_bfloat16* B2;
    int lda, ldb, Kseg;          // elements; total K = 3*Kseg
    float* C; int ldc;
    float alpha;                 // applied only when Z==1
    const float* addvec;         // only when Z==1; may be null
    size_t partStride;           // slice stride when Z>1
};

#define TILE_BYTES 16384                     // 128 rows x 128B
#define BUF_BYTES  (2 * TILE_BYTES)          // A + B per stage
#define GSMEM      (2 * BUF_BYTES)           // 65536

__global__ void __launch_bounds__(256, 2) mma_gemm(GemmArgs g) {
    extern __shared__ char smem[];
    const uint32_t sbase = smem_to_u32(smem);
    const int tid = threadIdx.x;
    const int wid = tid >> 5, lane = tid & 31;
    const int m0 = blockIdx.y * 128, n0 = blockIdx.x * 128;
    const int z = blockIdx.z, Z = gridDim.z;

    const int cps = g.Kseg >> 6;        // 64-wide chunks per segment
    const int ncz = (cps * 3) / Z;      // chunks for this z slice
    const int c0 = z * ncz, c1 = c0 + ncz;

    const __nv_bfloat16* As[3] = {g.A0, g.A1, g.A2};
    const __nv_bfloat16* Bs[3] = {g.B0, g.B1, g.B2};

    // ---- loader lane mapping: 32 rows x 8 col-groups (16B) per pass, 4 passes ----
    const int lrow = tid >> 3;
    const int lc16 = tid & 7;

    // ---- issue one chunk's cp.async (A+B tiles) into buffer buf ----
    auto issue = [&](int c, int buf) {
        const int seg = c / cps;
        const int k0 = (c - seg * cps) << 6;
        const __nv_bfloat16* Ap = As[seg] + (size_t)m0 * g.lda + k0;
        const __nv_bfloat16* Bp = Bs[seg] + (size_t)n0 * g.ldb + k0;
        const uint32_t abase = sbase + buf * BUF_BYTES;
        const uint32_t bbase = abase + TILE_BYTES;
        #pragma unroll
        for (int p = 0; p < 4; p++) {
            const int row = lrow + p * 32;
            const uint32_t so = row * 128 + ((lc16 ^ (row & 7)) << 4);
            cp_async16(abase + so, Ap + (size_t)row * g.lda + lc16 * 8);
            cp_async16(bbase + so, Bp + (size_t)row * g.ldb + lc16 * 8);
        }
        asm volatile("cp.async.commit_group;" ::: "memory");
    };

    // ---- warp tile bases ----
    const int wm = wid & 1;        // 0..1  -> 64 rows each
    const int wn = wid >> 1;       // 0..3  -> 32 cols each
    const int t15 = lane & 15;
    const int khalf = (lane >> 4) & 1;     // 0: k0-7, 1: k8-15 within a k16 step

    float acc[4][4][4];
    #pragma unroll
    for (int i = 0; i < 4; i++)
        #pragma unroll
        for (int j = 0; j < 4; j++)
            #pragma unroll
            for (int q = 0; q < 4; q++) acc[i][j][q] = 0.f;

    issue(c0, 0);
    for (int c = c0; c < c1; c++) {
        const int buf = (c - c0) & 1;
        if (c + 1 < c1) {
            issue(c + 1, buf ^ 1);
            asm volatile("cp.async.wait_group 1;" ::: "memory");
        } else {
            asm volatile("cp.async.wait_group 0;" ::: "memory");
        }
        __syncthreads();

        const uint32_t abase = sbase + buf * BUF_BYTES;
        const uint32_t bbase = abase + TILE_BYTES;
        #pragma unroll
        for (int kk = 0; kk < 4; kk++) {           // 4 k16 steps per 64-chunk
            const int c16 = kk * 2 + khalf;        // logical 16B column
            uint32_t afr[4][4], bfr[2][4];
            #pragma unroll
            for (int mt = 0; mt < 4; mt++) {
                const int row = wm * 64 + mt * 16 + t15;
                ldmatrix_x4(afr[mt], abase + row * 128 + ((c16 ^ (row & 7)) << 4));
            }
            #pragma unroll
            for (int h = 0; h < 2; h++) {
                const int row = wn * 32 + h * 16 + t15;
                ldmatrix_x4(bfr[h], bbase + row * 128 + ((c16 ^ (row & 7)) << 4));
            }
            #pragma unroll
            for (int mt = 0; mt < 4; mt++) {
                #pragma unroll
                for (int h = 0; h < 2; h++) {
                    mma_16816(acc[mt][h * 2 + 0], afr[mt], bfr[h][0], bfr[h][2]);
                    mma_16816(acc[mt][h * 2 + 1], afr[mt], bfr[h][1], bfr[h][3]);
                }
            }
        }
        __syncthreads();
    }

    // ---- epilogue: registers -> global ----
    float* Cb = (Z == 1) ? g.C : (g.C + (size_t)z * g.partStride);
    #pragma unroll
    for (int mt = 0; mt < 4; mt++) {
        const int row = m0 + wm * 64 + mt * 16 + (lane >> 2);
        #pragma unroll
        for (int nt = 0; nt < 4; nt++) {
            const int col = n0 + wn * 32 + nt * 8 + 2 * (lane & 3);
            float* p0 = Cb + (size_t)row * g.ldc + col;
            float* p1 = p0 + 8 * g.ldc;
            if (Z == 1) {
                float av0 = 0.f, av1 = 0.f;
                if (g.addvec) { av0 = g.addvec[col]; av1 = g.addvec[col + 1]; }
                p0[0] = g.alpha * acc[mt][nt][0] + av0;
                p0[1] = g.alpha * acc[mt][nt][1] + av1;
                p1[0] = g.alpha * acc[mt][nt][2] + av0;
                p1[1] = g.alpha * acc[mt][nt][3] + av1;
            } else {
                p0[0] = acc[mt][nt][0];
                p0[1] = acc[mt][nt][1];
                p1[0] = acc[mt][nt][2];
                p1[1] = acc[mt][nt][3];
            }
        }
    }
}

// ======================= split-K slice reduction: C = alpha * sum_z part[z] =======================
__global__ void reduce_zslices(const float* __restrict__ part, float* __restrict__ C,
                               int nvec4, int Z, float alpha) {
    int i = blockIdx.x * 256 + threadIdx.x;
    if (i >= nvec4) return;
    const float4* p4 = (const float4*)part;
    float4 s = p4[i];
    for (int zz = 1; zz < Z; zz++) {
        float4 t = p4[i + (size_t)zz * nvec4];
        s.x += t.x; s.y += t.y; s.z += t.z; s.w += t.w;
    }
    s.x *= alpha; s.y *= alpha; s.z *= alpha; s.w *= alpha;
    ((float4*)C)[i] = s;
}

// ======================= fp32 -> bf16 hi/lo split kernels =======================
__global__ void split_n_kernel(const float* __restrict__ in, __nv_bfloat16* __restrict__ hi,
                               __nv_bfloat16* __restrict__ lo, int n) {
    int i = blockIdx.x * 256 + threadIdx.x;
    if (i < n) {
        float v = in[i];
        __nv_bfloat16 h = __float2bfloat16(v);
        hi[i] = h;
        lo[i] = __float2bfloat16(v - __bfloat162float(h));
    }
}
// out[c][r] = split(in[r][c]); in: [R][C]
__global__ void split_t_kernel(const float* __restrict__ in, __nv_bfloat16* __restrict__ hi,
                               __nv_bfloat16* __restrict__ lo, int R, int C) {
    __shared__ float t[32][33];
    const int bx = blockIdx.x * 32;
    const int by = blockIdx.y * 32;
    const int x = threadIdx.x, y = threadIdx.y;
    #pragma unroll
    for (int i = 0; i < 32; i += 8)
        t[y + i][x] = in[(size_t)(by + y + i) * C + bx + x];
    __syncthreads();
    #pragma unroll
    for (int i = 0; i < 32; i += 8) {
        float v = t[x][y + i];
        __nv_bfloat16 h = __float2bfloat16(v);
        size_t o = (size_t)(bx + y + i) * R + by + x;
        hi[o] = h;
        lo[o] = __float2bfloat16(v - __bfloat162float(h));
    }
}

// ======================= small SIMT helpers =======================
__global__ void colsum_part(const float* __restrict__ x, float* __restrict__ part) {
    int j = blockIdx.x * 256 + threadIdx.x;
    int nb = blockIdx.y;
    float s = 0.f;
    int n0 = nb * (NROWS / 32);
    for (int n = n0; n < n0 + (NROWS / 32); n++) s += x[n * H + j];
    part[nb * H + j] = s;
}
__global__ void reduce_part(const float* __restrict__ part, float* __restrict__ out,
                            int cnt, float scale) {
    int j = blockIdx.x * 256 + threadIdx.x;
    float s = 0.f;
    for (int i = 0; i < cnt; i++) s += part[i * H + j];
    out[j] = s * scale;
}
__global__ void matvec_k(const float* __restrict__ W, const float* __restrict__ v,
                         float* __restrict__ out) {
    int row = blockIdx.x * 8 + (threadIdx.x >> 5);
    int lane = threadIdx.x & 31;
    float s = 0.f;
    for (int k = lane; k < H; k += 32) s += W[row * H + k] * v[k];
    #pragma unroll
    for (int o = 16; o > 0; o >>= 1) s += __shfl_xor_sync(0xffffffffu, s, o);
    if (lane == 0) out[row] = s;
}
__global__ void rank1_k(float* __restrict__ M, const float* __restrict__ ks,
                        const float* __restrict__ bk, const float* __restrict__ vs,
                        const float* __restrict__ bv) {
    int idx = blockIdx.x * 256 + threadIdx.x;
    int i = idx >> 10, j = idx & 1023;
    M[idx] += ks[i] * bv[j] + bk[i] * (vs[j] + 8192.0f * bv[j]);
}
__global__ void cvec_part(const float* __restrict__ M, const float* __restrict__ b,
                          float* __restrict__ part) {
    int j = blockIdx.x * 256 + threadIdx.x;
    int ib = blockIdx.y;
    float s = 0.f;
    for (int i = ib * 64; i < ib * 64 + 64; i++) s += M[i * H + j] * b[i];
    part[ib * H + j] = s;
}

// ======================= launch =======================
extern "C" void kernel_launch(void* const* d_in, const int* in_sizes, int n_in,
                              void* d_out, int out_size) {
    const float* x  = (const float*)d_in[0];
    const float* Wq = (const float*)d_in[1];
    const float* bq = (const float*)d_in[2];
    const float* Wk = (const float*)d_in[3];
    const float* bk = (const float*)d_in[4];
    const float* Wv = (const float*)d_in[5];
    const float* bv = (const float*)d_in[6];
    float* out = (float*)d_out;

    cudaFuncSetAttribute(mma_gemm, cudaFuncAttributeMaxDynamicSharedMemorySize, GSMEM);

    float *G, *T, *M, *P, *cpart, *spart, *s, *ks, *vs, *c;
    cudaGetSymbolAddress((void**)&G, g_G);
    cudaGetSymbolAddress((void**)&T, g_T);
    cudaGetSymbolAddress((void**)&M, g_M);
    cudaGetSymbolAddress((void**)&P, g_P);
    cudaGetSymbolAddress((void**)&cpart, g_cpart);
    cudaGetSymbolAddress((void**)&spart, g_spart);
    cudaGetSymbolAddress((void**)&s, g_s);
    cudaGetSymbolAddress((void**)&ks, g_ks);
    cudaGetSymbolAddress((void**)&vs, g_vs);
    cudaGetSymbolAddress((void**)&c, g_c);

    __nv_bfloat16 *xt_hi, *xt_lo, *x_hi, *x_lo, *wk_hi, *wk_lo, *wv_hi, *wv_lo;
    __nv_bfloat16 *wqt_hi, *wqt_lo, *gh, *gl, *th, *tl, *mth, *mtl, *pth, *ptl;
    cudaGetSymbolAddress((void**)&xt_hi, g_xt_hi);
    cudaGetSymbolAddress((void**)&xt_lo, g_xt_lo);
    cudaGetSymbolAddress((void**)&x_hi,  g_x_hi);
    cudaGetSymbolAddress((void**)&x_lo,  g_x_lo);
    cudaGetSymbolAddress((void**)&wk_hi, g_wk_hi);
    cudaGetSymbolAddress((void**)&wk_lo, g_wk_lo);
    cudaGetSymbolAddress((void**)&wv_hi, g_wv_hi);
    cudaGetSymbolAddress((void**)&wv_lo, g_wv_lo);
    cudaGetSymbolAddress((void**)&wqt_hi, g_wqt_hi);
    cudaGetSymbolAddress((void**)&wqt_lo, g_wqt_lo);
    cudaGetSymbolAddress((void**)&gh, g_g_hi);
    cudaGetSymbolAddress((void**)&gl, g_g_lo);
    cudaGetSymbolAddress((void**)&th, g_t_hi);
    cudaGetSymbolAddress((void**)&tl, g_t_lo);
    cudaGetSymbolAddress((void**)&mth, g_mt_hi);
    cudaGetSymbolAddress((void**)&mtl, g_mt_lo);
    cudaGetSymbolAddress((void**)&pth, g_pt_hi);
    cudaGetSymbolAddress((void**)&ptl, g_pt_lo);

    const float inv_sqrt_h = 0.03125f;   // 1/sqrt(1024)
    const int NV4 = (H * H) / 4;
    dim3 tb(32, 8);

    // ---- input splits ----
    split_t_kernel<<<dim3(H / 32, NROWS / 32), tb>>>(x, xt_hi, xt_lo, NROWS, H);
    split_n_kernel<<<(NROWS * H) / 256, 256>>>(x, x_hi, x_lo, NROWS * H);
    split_n_kernel<<<(H * H) / 256, 256>>>(Wk, wk_hi, wk_lo, H * H);
    split_n_kernel<<<(H * H) / 256, 256>>>(Wv, wv_hi, wv_lo, H * H);
    split_t_kernel<<<dim3(H / 32, H / 32), tb>>>(Wq, wqt_hi, wqt_lo, H, H);

    // ---- column sums -> s; ks = Wk s; vs = Wv s ----
    colsum_part<<<dim3(4, 32), 256>>>(x, spart);
    reduce_part<<<4, 256>>>(spart, s, 32, 1.0f);
    matvec_k<<<128, 256>>>(Wk, s, ks);
    matvec_k<<<128, 256>>>(Wv, s, vs);

    // ---- G = x^T x  (K = 3*8192, Z = 6) ----
    {
        GemmArgs a = {xt_hi, xt_hi, xt_lo,  xt_hi, xt_lo, xt_hi,
                      NROWS, NROWS, NROWS, cpart, H, 1.0f, nullptr, (size_t)H * H};
        mma_gemm<<<dim3(8, 8, 6), 256, GSMEM>>>(a);
        reduce_zslices<<<NV4 / 256, 256>>>(cpart, G, NV4, 6, 1.0f);
    }
    split_n_kernel<<<(H * H) / 256, 256>>>(G, gh, gl, H * H);   // G symmetric

    // ---- T = Wk @ G  (Z = 3) ----
    {
        GemmArgs a = {wk_hi, wk_hi, wk_lo,  gh, gl, gh,
                      H, H, H, cpart, H, 1.0f, nullptr, (size_t)H * H};
        mma_gemm<<<dim3(8, 8, 3), 256, GSMEM>>>(a);
        reduce_zslices<<<NV4 / 256, 256>>>(cpart, T, NV4, 3, 1.0f);
    }
    split_n_kernel<<<(H * H) / 256, 256>>>(T, th, tl, H * H);

    // ---- M = T @ Wv^T  (Z = 3) ----
    {
        GemmArgs a = {th, th, tl,  wv_hi, wv_lo, wv_hi,
                      H, H, H, cpart, H, 1.0f, nullptr, (size_t)H * H};
        mma_gemm<<<dim3(8, 8, 3), 256, GSMEM>>>(a);
        reduce_zslices<<<NV4 / 256, 256>>>(cpart, M, NV4, 3, 1.0f);
    }
    rank1_k<<<4096, 256>>>(M, ks, bk, vs, bv);

    // ---- P = Wq^T @ M / sqrt(H)  (Z = 3) ----
    split_t_kernel<<<dim3(H / 32, H / 32), tb>>>(M, mth, mtl, H, H);
    {
        GemmArgs a = {wqt_hi, wqt_hi, wqt_lo,  mth, mtl, mth,
                      H, H, H, cpart, H, 1.0f, nullptr, (size_t)H * H};
        mma_gemm<<<dim3(8, 8, 3), 256, GSMEM>>>(a);
        reduce_zslices<<<NV4 / 256, 256>>>(cpart, P, NV4, 3, inv_sqrt_h);
    }

    // ---- c = M^T bq / sqrt(H) ----
    cvec_part<<<dim3(4, 16), 256>>>(M, bq, spart);
    reduce_part<<<4, 256>>>(spart, c, 16, inv_sqrt_h);

    // ---- out = x @ P + 1 c^T  (Z = 1, fused epilogue) ----
    split_t_kernel<<<dim3(H / 32, H / 32), tb>>>(P, pth, ptl, H, H);
    {
        GemmArgs a = {x_hi, x_hi, x_lo,  pth, ptl, pth,
                      H, H, H, out, H, 1.0f, c, 0};
        mma_gemm<<<dim3(8, NROWS / 128, 1), 256, GSMEM>>>(a);
    }
}

// round 9
// speedup vs baseline: 1.5792x; 1.0441x over previous
#include <cuda_runtime.h>
#include <cuda_bf16.h>
#include <cstdint>
#include <cstddef>

#define NROWS 8192
#define H 1024

// ======================= helpers =======================
__device__ __forceinline__ uint32_t smem_to_u32(const void* p) {
    uint32_t a;
    asm("{ .reg .u64 t; cvta.to.shared.u64 t, %1; cvt.u32.u64 %0, t; }" : "=r"(a) : "l"(p));
    return a;
}
__device__ __forceinline__ void ldmatrix_x4(uint32_t* r, uint32_t addr) {
    asm volatile("ldmatrix.sync.aligned.m8n8.x4.shared.b16 {%0,%1,%2,%3}, [%4];"
                 : "=r"(r[0]), "=r"(r[1]), "=r"(r[2]), "=r"(r[3]) : "r"(addr));
}
__device__ __forceinline__ void mma_16816(float* d, const uint32_t* a, uint32_t b0, uint32_t b1) {
    asm volatile(
        "mma.sync.aligned.m16n8k16.row.col.f32.bf16.bf16.f32 "
        "{%0,%1,%2,%3}, {%4,%5,%6,%7}, {%8,%9}, {%0,%1,%2,%3};"
        : "+f"(d[0]), "+f"(d[1]), "+f"(d[2]), "+f"(d[3])
        : "r"(a[0]), "r"(a[1]), "r"(a[2]), "r"(a[3]), "r"(b0), "r"(b1));
}
__device__ __forceinline__ void cp_async16(uint32_t saddr, const void* gaddr) {
    asm volatile("cp.async.cg.shared.global [%0], [%1], 16;" :: "r"(saddr), "l"(gaddr));
}
__device__ __forceinline__ void bf16_split(float v, __nv_bfloat16& h, __nv_bfloat16& l) {
    h = __float2bfloat16(v);
    l = __float2bfloat16(v - __bfloat162float(h));
}

// ======================= scratch (device globals only) =======================
__device__ __align__(256) float g_M[H * H];
__device__ __align__(256) float g_cpart[8 * H * H];   // split-K partials (max Z=8)
__device__ __align__(256) float g_spart[32 * H];
__device__ float g_s[H];
__device__ float g_ks[H];
__device__ float g_vs[H];
__device__ float g_c[H];

__device__ __align__(256) __nv_bfloat16 g_xt_hi[H * NROWS];
__device__ __align__(256) __nv_bfloat16 g_xt_lo[H * NROWS];
__device__ __align__(256) __nv_bfloat16 g_x_hi[NROWS * H];
__device__ __align__(256) __nv_bfloat16 g_x_lo[NROWS * H];
__device__ __align__(256) __nv_bfloat16 g_wk_hi[H * H], g_wk_lo[H * H];
__device__ __align__(256) __nv_bfloat16 g_wv_hi[H * H], g_wv_lo[H * H];
__device__ __align__(256) __nv_bfloat16 g_wqt_hi[H * H], g_wqt_lo[H * H];
__device__ __align__(256) __nv_bfloat16 g_g_hi[H * H],  g_g_lo[H * H];
__device__ __align__(256) __nv_bfloat16 g_t_hi[H * H],  g_t_lo[H * H];
__device__ __align__(256) __nv_bfloat16 g_mt_hi[H * H], g_mt_lo[H * H];
__device__ __align__(256) __nv_bfloat16 g_pt_hi[H * H], g_pt_lo[H * H];

// ======================= HMMA GEMM: C = alpha * A @ B^T (+ addvec) =======================
// 256x128 CTA tile, 8 warps (4m x 2n), 64x64 warp tile, K-chunk 64, 3-stage cp.async ring.
// tri=1: lower-band block decode for symmetric x^T x (grid.x = 20 flattened blocks).
struct GemmArgs {
    const __nv_bfloat16* A0; const __nv_bfloat16* A1; const __nv_bfloat16* A2;
    const __nv_bfloat16* B0; const __nv_bfloat16* B1; const __nv_bfloat16* B2;
    int lda, ldb, Kseg;          // elements; total K = 3*Kseg
    float* C; int ldc;
    float alpha;                 // applied only when Z==1
    const float* addvec;         // only when Z==1; may be null
    size_t partStride;           // slice stride when Z>1
    int tri;
};

#define STAGE   49152                        // A 32KB + B 16KB
#define NSTAGE  3
#define GSMEM   (NSTAGE * STAGE)             // 147456

__global__ void __launch_bounds__(256, 1) mma_gemm(GemmArgs g) {
    extern __shared__ char smem[];
    const uint32_t sbase = smem_to_u32(smem);
    const int tid = threadIdx.x;
    const int wid = tid >> 5, lane = tid & 31;
    int bx, by;
    if (g.tri) {   // lower-band blocks: by*(by+1) cumulative bases {0,2,6,12}
        const int idx = blockIdx.x;
        by = (idx < 2) ? 0 : (idx < 6) ? 1 : (idx < 12) ? 2 : 3;
        bx = idx - by * (by + 1);
    } else { bx = blockIdx.x; by = blockIdx.y; }
    const int m0 = by * 256, n0 = bx * 128;
    const int z = blockIdx.z, Z = gridDim.z;

    const int cps = g.Kseg >> 6;
    const int ncz = (cps * 3) / Z;
    const int c0 = z * ncz, c1 = c0 + ncz;

    const __nv_bfloat16* As[3] = {g.A0, g.A1, g.A2};
    const __nv_bfloat16* Bs[3] = {g.B0, g.B1, g.B2};

    const int lrow = tid >> 3;          // 0..31
    const int lc16 = tid & 7;           // 16B column group

    auto issue = [&](int c, int st) {
        const int seg = c / cps;
        const int k0 = (c - seg * cps) << 6;
        const __nv_bfloat16* Ap = As[seg] + (size_t)m0 * g.lda + k0;
        const __nv_bfloat16* Bp = Bs[seg] + (size_t)n0 * g.ldb + k0;
        const uint32_t abase = sbase + st * STAGE;
        const uint32_t bbase = abase + 32768;
        #pragma unroll
        for (int p = 0; p < 8; p++) {   // A: 256 rows
            const int row = lrow + p * 32;
            const uint32_t so = row * 128 + ((lc16 ^ (row & 7)) << 4);
            cp_async16(abase + so, Ap + (size_t)row * g.lda + lc16 * 8);
        }
        #pragma unroll
        for (int p = 0; p < 4; p++) {   // B: 128 rows
            const int row = lrow + p * 32;
            const uint32_t so = row * 128 + ((lc16 ^ (row & 7)) << 4);
            cp_async16(bbase + so, Bp + (size_t)row * g.ldb + lc16 * 8);
        }
        asm volatile("cp.async.commit_group;" ::: "memory");
    };

    const int wm = wid >> 1;            // 0..3 -> 64 rows
    const int wn = wid & 1;             // 0..1 -> 64 cols
    const int t15 = lane & 15;
    const int khalf = (lane >> 4) & 1;

    float acc[4][8][4];
    #pragma unroll
    for (int i = 0; i < 4; i++)
        #pragma unroll
        for (int j = 0; j < 8; j++)
            #pragma unroll
            for (int q = 0; q < 4; q++) acc[i][j][q] = 0.f;

    issue(c0, 0);
    if (c0 + 1 < c1) issue(c0 + 1, 1);
    for (int c = c0; c < c1; c++) {
        const int st = (c - c0) % NSTAGE;
        if (c + 1 < c1) asm volatile("cp.async.wait_group 1;" ::: "memory");
        else            asm volatile("cp.async.wait_group 0;" ::: "memory");
        __syncthreads();
        if (c + 2 < c1) issue(c + 2, (st + 2) % NSTAGE);

        const uint32_t abase = sbase + st * STAGE;
        const uint32_t bbase = abase + 32768;
        #pragma unroll
        for (int kk = 0; kk < 4; kk++) {
            const int c16 = kk * 2 + khalf;
            uint32_t afr[4][4], bfr[4][4];
            #pragma unroll
            for (int mt = 0; mt < 4; mt++) {
                const int row = wm * 64 + mt * 16 + t15;
                ldmatrix_x4(afr[mt], abase + row * 128 + ((c16 ^ (row & 7)) << 4));
            }
            #pragma unroll
            for (int nt = 0; nt < 4; nt++) {
                const int row = wn * 64 + nt * 16 + t15;
                ldmatrix_x4(bfr[nt], bbase + row * 128 + ((c16 ^ (row & 7)) << 4));
            }
            #pragma unroll
            for (int mt = 0; mt < 4; mt++) {
                #pragma unroll
                for (int nt = 0; nt < 4; nt++) {
                    mma_16816(acc[mt][nt * 2 + 0], afr[mt], bfr[nt][0], bfr[nt][2]);
                    mma_16816(acc[mt][nt * 2 + 1], afr[mt], bfr[nt][1], bfr[nt][3]);
                }
            }
        }
        __syncthreads();
    }

    float* Cb = (Z == 1) ? g.C : (g.C + (size_t)z * g.partStride);
    #pragma unroll
    for (int mt = 0; mt < 4; mt++) {
        const int row = m0 + wm * 64 + mt * 16 + (lane >> 2);
        #pragma unroll
        for (int nt = 0; nt < 4; nt++) {
            #pragma unroll
            for (int gg = 0; gg < 2; gg++) {
                const int col = n0 + wn * 64 + nt * 16 + gg * 8 + 2 * (lane & 3);
                float* acc4 = acc[mt][nt * 2 + gg];
                float* p0 = Cb + (size_t)row * g.ldc + col;
                float* p1 = p0 + 8 * g.ldc;
                if (Z == 1) {
                    float av0 = 0.f, av1 = 0.f;
                    if (g.addvec) { av0 = g.addvec[col]; av1 = g.addvec[col + 1]; }
                    p0[0] = g.alpha * acc4[0] + av0;
                    p0[1] = g.alpha * acc4[1] + av1;
                    p1[0] = g.alpha * acc4[2] + av0;
                    p1[1] = g.alpha * acc4[3] + av1;
                } else {
                    p0[0] = acc4[0]; p0[1] = acc4[1];
                    p1[0] = acc4[2]; p1[1] = acc4[3];
                }
            }
        }
    }
}

// ======================= fused reductions =======================
// G: sum Z slices over the computed lower band, mirror the skipped upper blocks,
// emit bf16 hi/lo directly (no fp32 G). Tile 32x32, block (32,8).
__global__ void reduce_mirror_split(const float* __restrict__ part,
                                    __nv_bfloat16* __restrict__ hi,
                                    __nv_bfloat16* __restrict__ lo, int Z) {
    __shared__ float t[32][33];
    const int C = blockIdx.x * 32, R = blockIdx.y * 32;
    const int X = threadIdx.x, Y = threadIdx.y;
    const bool computed = ((C >> 7) <= 2 * (R >> 8) + 1);
    if (computed) {
        #pragma unroll
        for (int i = 0; i < 32; i += 8) {
            size_t o = (size_t)(R + Y + i) * H + C + X;
            float s = part[o];
            for (int zz = 1; zz < Z; zz++) s += part[o + (size_t)zz * H * H];
            __nv_bfloat16 h, l; bf16_split(s, h, l);
            hi[o] = h; lo[o] = l;
        }
    } else {
        #pragma unroll
        for (int i = 0; i < 32; i += 8) {
            size_t o = (size_t)(C + Y + i) * H + R + X;   // mirrored source
            float s = part[o];
            for (int zz = 1; zz < Z; zz++) s += part[o + (size_t)zz * H * H];
            t[Y + i][X] = s;
        }
        __syncthreads();
        #pragma unroll
        for (int i = 0; i < 32; i += 8) {
            float v = t[X][Y + i];
            size_t o = (size_t)(R + Y + i) * H + C + X;
            __nv_bfloat16 h, l; bf16_split(v, h, l);
            hi[o] = h; lo[o] = l;
        }
    }
}

// sum Z slices -> bf16 hi/lo (same layout)
__global__ void reduce_split_n(const float* __restrict__ part,
                               __nv_bfloat16* __restrict__ hi,
                               __nv_bfloat16* __restrict__ lo, int Z) {
    int i = blockIdx.x * 256 + threadIdx.x;
    float s = part[i];
    for (int zz = 1; zz < Z; zz++) s += part[i + (size_t)zz * H * H];
    __nv_bfloat16 h, l; bf16_split(s, h, l);
    hi[i] = h; lo[i] = l;
}

// sum Z slices + rank-1 corrections -> fp32 M
__global__ void reduce_rank1(const float* __restrict__ part, float* __restrict__ M,
                             const float* __restrict__ ks, const float* __restrict__ bk,
                             const float* __restrict__ vs, const float* __restrict__ bv,
                             int Z) {
    int idx = blockIdx.x * 256 + threadIdx.x;
    int r = idx >> 10, cc = idx & 1023;
    float s = part[idx];
    for (int zz = 1; zz < Z; zz++) s += part[idx + (size_t)zz * H * H];
    M[idx] = s + ks[r] * bv[cc] + bk[r] * (vs[cc] + 8192.0f * bv[cc]);
}

// sum Z slices, *alpha, emit TRANSPOSED bf16 hi/lo (for P -> pth/ptl)
__global__ void reduce_split_t(const float* __restrict__ part,
                               __nv_bfloat16* __restrict__ hi,
                               __nv_bfloat16* __restrict__ lo, int Z, float alpha) {
    __shared__ float t[32][33];
    const int C = blockIdx.x * 32, R = blockIdx.y * 32;
    const int X = threadIdx.x, Y = threadIdx.y;
    #pragma unroll
    for (int i = 0; i < 32; i += 8) {
        size_t o = (size_t)(R + Y + i) * H + C + X;
        float s = part[o];
        for (int zz = 1; zz < Z; zz++) s += part[o + (size_t)zz * H * H];
        t[Y + i][X] = alpha * s;
    }
    __syncthreads();
    #pragma unroll
    for (int i = 0; i < 32; i += 8) {
        float v = t[X][Y + i];                         // = P[R+X][C+Y+i]
        size_t o = (size_t)(C + Y + i) * H + R + X;    // pt[c][r]
        __nv_bfloat16 h, l; bf16_split(v, h, l);
        hi[o] = h; lo[o] = l;
    }
}

// ======================= split kernels =======================
// one pass over x: emit x_hi/x_lo (direct) + xt_hi/xt_lo (transposed)
__global__ void split_x_fused(const float* __restrict__ x,
                              __nv_bfloat16* __restrict__ xh, __nv_bfloat16* __restrict__ xl,
                              __nv_bfloat16* __restrict__ xth, __nv_bfloat16* __restrict__ xtl) {
    __shared__ float t[32][33];
    const int bxc = blockIdx.x * 32;   // col base (H dim)
    const int byr = blockIdx.y * 32;   // row base (NROWS dim)
    const int X = threadIdx.x, Y = threadIdx.y;
    #pragma unroll
    for (int i = 0; i < 32; i += 8) {
        size_t o = (size_t)(byr + Y + i) * H + bxc + X;
        float v = x[o];
        t[Y + i][X] = v;
        __nv_bfloat16 h, l; bf16_split(v, h, l);
        xh[o] = h; xl[o] = l;
    }
    __syncthreads();
    #pragma unroll
    for (int i = 0; i < 32; i += 8) {
        float v = t[X][Y + i];                              // = x[byr+X][bxc+Y+i]
        size_t o = (size_t)(bxc + Y + i) * NROWS + byr + X; // xt[c][r]
        __nv_bfloat16 h, l; bf16_split(v, h, l);
        xth[o] = h; xtl[o] = l;
    }
}
__global__ void split_n_kernel(const float* __restrict__ in, __nv_bfloat16* __restrict__ hi,
                               __nv_bfloat16* __restrict__ lo, int n) {
    int i = blockIdx.x * 256 + threadIdx.x;
    if (i < n) { __nv_bfloat16 h, l; bf16_split(in[i], h, l); hi[i] = h; lo[i] = l; }
}
__global__ void split_t_kernel(const float* __restrict__ in, __nv_bfloat16* __restrict__ hi,
                               __nv_bfloat16* __restrict__ lo, int R, int C) {
    __shared__ float t[32][33];
    const int bx = blockIdx.x * 32;
    const int by = blockIdx.y * 32;
    const int x = threadIdx.x, y = threadIdx.y;
    #pragma unroll
    for (int i = 0; i < 32; i += 8)
        t[y + i][x] = in[(size_t)(by + y + i) * C + bx + x];
    __syncthreads();
    #pragma unroll
    for (int i = 0; i < 32; i += 8) {
        float v = t[x][y + i];
        size_t o = (size_t)(bx + y + i) * R + by + x;
        __nv_bfloat16 h, l; bf16_split(v, h, l);
        hi[o] = h; lo[o] = l;
    }
}

// ======================= small SIMT helpers =======================
__global__ void colsum_part(const float* __restrict__ x, float* __restrict__ part) {
    int j = blockIdx.x * 256 + threadIdx.x;
    int nb = blockIdx.y;
    float s = 0.f;
    int n0 = nb * (NROWS / 32);
    for (int n = n0; n < n0 + (NROWS / 32); n++) s += x[n * H + j];
    part[nb * H + j] = s;
}
__global__ void reduce_part(const float* __restrict__ part, float* __restrict__ out,
                            int cnt, float scale) {
    int j = blockIdx.x * 256 + threadIdx.x;
    float s = 0.f;
    for (int i = 0; i < cnt; i++) s += part[i * H + j];
    out[j] = s * scale;
}
__global__ void matvec_k(const float* __restrict__ W, const float* __restrict__ v,
                         float* __restrict__ out) {
    int row = blockIdx.x * 8 + (threadIdx.x >> 5);
    int lane = threadIdx.x & 31;
    float s = 0.f;
    for (int k = lane; k < H; k += 32) s += W[row * H + k] * v[k];
    #pragma unroll
    for (int o = 16; o > 0; o >>= 1) s += __shfl_xor_sync(0xffffffffu, s, o);
    if (lane == 0) out[row] = s;
}
__global__ void cvec_part(const float* __restrict__ M, const float* __restrict__ b,
                          float* __restrict__ part) {
    int j = blockIdx.x * 256 + threadIdx.x;
    int ib = blockIdx.y;
    float s = 0.f;
    for (int i = ib * 64; i < ib * 64 + 64; i++) s += M[i * H + j] * b[i];
    part[ib * H + j] = s;
}

// ======================= launch =======================
extern "C" void kernel_launch(void* const* d_in, const int* in_sizes, int n_in,
                              void* d_out, int out_size) {
    const float* x  = (const float*)d_in[0];
    const float* Wq = (const float*)d_in[1];
    const float* bq = (const float*)d_in[2];
    const float* Wk = (const float*)d_in[3];
    const float* bk = (const float*)d_in[4];
    const float* Wv = (const float*)d_in[5];
    const float* bv = (const float*)d_in[6];
    float* out = (float*)d_out;

    cudaFuncSetAttribute(mma_gemm, cudaFuncAttributeMaxDynamicSharedMemorySize, GSMEM);

    float *M, *cpart, *spart, *s, *ks, *vs, *c;
    cudaGetSymbolAddress((void**)&M, g_M);
    cudaGetSymbolAddress((void**)&cpart, g_cpart);
    cudaGetSymbolAddress((void**)&spart, g_spart);
    cudaGetSymbolAddress((void**)&s, g_s);
    cudaGetSymbolAddress((void**)&ks, g_ks);
    cudaGetSymbolAddress((void**)&vs, g_vs);
    cudaGetSymbolAddress((void**)&c, g_c);

    __nv_bfloat16 *xt_hi, *xt_lo, *x_hi, *x_lo, *wk_hi, *wk_lo, *wv_hi, *wv_lo;
    __nv_bfloat16 *wqt_hi, *wqt_lo, *gh, *gl, *th, *tl, *mth, *mtl, *pth, *ptl;
    cudaGetSymbolAddress((void**)&xt_hi, g_xt_hi);
    cudaGetSymbolAddress((void**)&xt_lo, g_xt_lo);
    cudaGetSymbolAddress((void**)&x_hi,  g_x_hi);
    cudaGetSymbolAddress((void**)&x_lo,  g_x_lo);
    cudaGetSymbolAddress((void**)&wk_hi, g_wk_hi);
    cudaGetSymbolAddress((void**)&wk_lo, g_wk_lo);
    cudaGetSymbolAddress((void**)&wv_hi, g_wv_hi);
    cudaGetSymbolAddress((void**)&wv_lo, g_wv_lo);
    cudaGetSymbolAddress((void**)&wqt_hi, g_wqt_hi);
    cudaGetSymbolAddress((void**)&wqt_lo, g_wqt_lo);
    cudaGetSymbolAddress((void**)&gh, g_g_hi);
    cudaGetSymbolAddress((void**)&gl, g_g_lo);
    cudaGetSymbolAddress((void**)&th, g_t_hi);
    cudaGetSymbolAddress((void**)&tl, g_t_lo);
    cudaGetSymbolAddress((void**)&mth, g_mt_hi);
    cudaGetSymbolAddress((void**)&mtl, g_mt_lo);
    cudaGetSymbolAddress((void**)&pth, g_pt_hi);
    cudaGetSymbolAddress((void**)&ptl, g_pt_lo);

    const float inv_sqrt_h = 0.03125f;
    const size_t PS = (size_t)H * H;
    dim3 tb(32, 8);

    // ---- splits ----
    split_x_fused<<<dim3(H / 32, NROWS / 32), tb>>>(x, x_hi, x_lo, xt_hi, xt_lo);
    split_n_kernel<<<(H * H) / 256, 256>>>(Wk, wk_hi, wk_lo, H * H);
    split_n_kernel<<<(H * H) / 256, 256>>>(Wv, wv_hi, wv_lo, H * H);
    split_t_kernel<<<dim3(H / 32, H / 32), tb>>>(Wq, wqt_hi, wqt_lo, H, H);

    // ---- s = colsum(x); ks = Wk s; vs = Wv s ----
    colsum_part<<<dim3(4, 32), 256>>>(x, spart);
    reduce_part<<<4, 256>>>(spart, s, 32, 1.0f);
    matvec_k<<<128, 256>>>(Wk, s, ks);
    matvec_k<<<128, 256>>>(Wv, s, vs);

    // ---- G = x^T x : symmetric, lower band only (20 blocks), Z = 8 ----
    {
        GemmArgs a = {xt_hi, xt_hi, xt_lo,  xt_hi, xt_lo, xt_hi,
                      NROWS, NROWS, NROWS, cpart, H, 1.0f, nullptr, PS, 1};
        mma_gemm<<<dim3(20, 1, 8), 256, GSMEM>>>(a);
        reduce_mirror_split<<<dim3(32, 32), tb>>>(cpart, gh, gl, 8);
    }

    // ---- T = Wk @ G  (Z = 4) ----
    {
        GemmArgs a = {wk_hi, wk_hi, wk_lo,  gh, gl, gh,
                      H, H, H, cpart, H, 1.0f, nullptr, PS, 0};
        mma_gemm<<<dim3(8, 4, 4), 256, GSMEM>>>(a);
        reduce_split_n<<<4096, 256>>>(cpart, th, tl, 4);
    }

    // ---- M = T @ Wv^T + rank-1  (Z = 4) ----
    {
        GemmArgs a = {th, th, tl,  wv_hi, wv_lo, wv_hi,
                      H, H, H, cpart, H, 1.0f, nullptr, PS, 0};
        mma_gemm<<<dim3(8, 4, 4), 256, GSMEM>>>(a);
        reduce_rank1<<<4096, 256>>>(cpart, M, ks, bk, vs, bv, 4);
    }
    split_t_kernel<<<dim3(H / 32, H / 32), tb>>>(M, mth, mtl, H, H);

    // ---- P = Wq^T @ M / sqrt(H)  (Z = 4), emitted directly as transposed split ----
    {
        GemmArgs a = {wqt_hi, wqt_hi, wqt_lo,  mth, mtl, mth,
                      H, H, H, cpart, H, 1.0f, nullptr, PS, 0};
        mma_gemm<<<dim3(8, 4, 4), 256, GSMEM>>>(a);
        reduce_split_t<<<dim3(32, 32), tb>>>(cpart, pth, ptl, 4, inv_sqrt_h);
    }

    // ---- c = M^T bq / sqrt(H) ----
    cvec_part<<<dim3(4, 16), 256>>>(M, bq, spart);
    reduce_part<<<4, 256>>>(spart, c, 16, inv_sqrt_h);

    // ---- out = x @ P + 1 c^T  (Z = 1, fused epilogue) ----
    {
        GemmArgs a = {x_hi, x_hi, x_lo,  pth, ptl, pth,
                      H, H, H, out, H, 1.0f, c, 0, 0};
        mma_gemm<<<dim3(8, NROWS / 256, 1), 256, GSMEM>>>(a);
    }
}

// round 10
// speedup vs baseline: 3.0258x; 1.9160x over previous
#include <cuda_runtime.h>
#include <cuda_fp16.h>
#include <cstdint>
#include <cstddef>

#define NROWS 8192
#define H 1024

// ======================= helpers =======================
__device__ __forceinline__ uint32_t smem_to_u32(const void* p) {
    uint32_t a;
    asm("{ .reg .u64 t; cvta.to.shared.u64 t, %1; cvt.u32.u64 %0, t; }" : "=r"(a) : "l"(p));
    return a;
}
__device__ __forceinline__ void ldmatrix_x4(uint32_t* r, uint32_t addr) {
    asm volatile("ldmatrix.sync.aligned.m8n8.x4.shared.b16 {%0,%1,%2,%3}, [%4];"
                 : "=r"(r[0]), "=r"(r[1]), "=r"(r[2]), "=r"(r[3]) : "r"(addr));
}
__device__ __forceinline__ void mma_16816(float* d, const uint32_t* a, uint32_t b0, uint32_t b1) {
    asm volatile(
        "mma.sync.aligned.m16n8k16.row.col.f32.f16.f16.f32 "
        "{%0,%1,%2,%3}, {%4,%5,%6,%7}, {%8,%9}, {%0,%1,%2,%3};"
        : "+f"(d[0]), "+f"(d[1]), "+f"(d[2]), "+f"(d[3])
        : "r"(a[0]), "r"(a[1]), "r"(a[2]), "r"(a[3]), "r"(b0), "r"(b1));
}
__device__ __forceinline__ void cp_async16(uint32_t saddr, const void* gaddr) {
    asm volatile("cp.async.cg.shared.global [%0], [%1], 16;" :: "r"(saddr), "l"(gaddr));
}
__device__ __forceinline__ void fp16_split(float v, __half& h, __half& l) {
    h = __float2half(v);
    l = __float2half(v - __half2float(h));
}

// ======================= scratch (device globals only) =======================
__device__ __align__(256) float g_M[H * H];
__device__ __align__(256) float g_cpart[8 * H * H];   // split-K partials (max Z=8)
__device__ __align__(256) float g_spart[32 * H];
__device__ float g_s[H];
__device__ float g_ks[H];
__device__ float g_vs[H];
__device__ float g_c[H];

__device__ __align__(256) __half g_xt_hi[H * NROWS];   // x^T fp16 hi/lo
__device__ __align__(256) __half g_xt_lo[H * NROWS];
__device__ __align__(256) __half g_x_h[NROWS * H];     // fp16(x), direct layout
__device__ __align__(256) __half g_wk_hi[H * H], g_wk_lo[H * H];
__device__ __align__(256) __half g_wv_hi[H * H], g_wv_lo[H * H];
__device__ __align__(256) __half g_wqt_hi[H * H], g_wqt_lo[H * H];
__device__ __align__(256) __half g_g_hi[H * H],  g_g_lo[H * H];
__device__ __align__(256) __half g_t_hi[H * H],  g_t_lo[H * H];
__device__ __align__(256) __half g_mt_hi[H * H], g_mt_lo[H * H];
__device__ __align__(256) __half g_pt_h[H * H];        // fp16(P)^T, single term

// ======================= HMMA GEMM: C = alpha * A @ B^T (+ addvec) =======================
// 256x128 CTA tile, 8 warps (4m x 2n), 64x64 warp tile, K-chunk 64, 3-stage cp.async ring.
// nseg segments of Kseg each (total K = nseg*Kseg).
// tri=1: lower-band block decode for symmetric x^T x (grid.x = 20 flattened blocks).
struct GemmArgs {
    const __half* A0; const __half* A1; const __half* A2;
    const __half* B0; const __half* B1; const __half* B2;
    int lda, ldb, Kseg;
    float* C; int ldc;
    float alpha;                 // applied only when Z==1
    const float* addvec;         // only when Z==1; may be null
    size_t partStride;           // slice stride when Z>1
    int tri;
    int nseg;
};

#define STAGE   49152                        // A 32KB + B 16KB
#define NSTAGE  3
#define GSMEM   (NSTAGE * STAGE)             // 147456

__global__ void __launch_bounds__(256, 1) mma_gemm(GemmArgs g) {
    extern __shared__ char smem[];
    const uint32_t sbase = smem_to_u32(smem);
    const int tid = threadIdx.x;
    const int wid = tid >> 5, lane = tid & 31;
    int bx, by;
    if (g.tri) {   // lower-band blocks: cumulative bases {0,2,6,12}
        const int idx = blockIdx.x;
        by = (idx < 2) ? 0 : (idx < 6) ? 1 : (idx < 12) ? 2 : 3;
        bx = idx - by * (by + 1);
    } else { bx = blockIdx.x; by = blockIdx.y; }
    const int m0 = by * 256, n0 = bx * 128;
    const int z = blockIdx.z, Z = gridDim.z;

    const int cps = g.Kseg >> 6;
    const int ncz = (cps * g.nseg) / Z;
    const int c0 = z * ncz, c1 = c0 + ncz;

    const __half* As[3] = {g.A0, g.A1, g.A2};
    const __half* Bs[3] = {g.B0, g.B1, g.B2};

    const int lrow = tid >> 3;          // 0..31
    const int lc16 = tid & 7;           // 16B column group

    auto issue = [&](int c, int st) {
        const int seg = c / cps;
        const int k0 = (c - seg * cps) << 6;
        const __half* Ap = As[seg] + (size_t)m0 * g.lda + k0;
        const __half* Bp = Bs[seg] + (size_t)n0 * g.ldb + k0;
        const uint32_t abase = sbase + st * STAGE;
        const uint32_t bbase = abase + 32768;
        #pragma unroll
        for (int p = 0; p < 8; p++) {   // A: 256 rows
            const int row = lrow + p * 32;
            const uint32_t so = row * 128 + ((lc16 ^ (row & 7)) << 4);
            cp_async16(abase + so, Ap + (size_t)row * g.lda + lc16 * 8);
        }
        #pragma unroll
        for (int p = 0; p < 4; p++) {   // B: 128 rows
            const int row = lrow + p * 32;
            const uint32_t so = row * 128 + ((lc16 ^ (row & 7)) << 4);
            cp_async16(bbase + so, Bp + (size_t)row * g.ldb + lc16 * 8);
        }
        asm volatile("cp.async.commit_group;" ::: "memory");
    };

    const int wm = wid >> 1;            // 0..3 -> 64 rows
    const int wn = wid & 1;             // 0..1 -> 64 cols
    const int t15 = lane & 15;
    const int khalf = (lane >> 4) & 1;

    float acc[4][8][4];
    #pragma unroll
    for (int i = 0; i < 4; i++)
        #pragma unroll
        for (int j = 0; j < 8; j++)
            #pragma unroll
            for (int q = 0; q < 4; q++) acc[i][j][q] = 0.f;

    issue(c0, 0);
    if (c0 + 1 < c1) issue(c0 + 1, 1);
    for (int c = c0; c < c1; c++) {
        const int st = (c - c0) % NSTAGE;
        if (c + 1 < c1) asm volatile("cp.async.wait_group 1;" ::: "memory");
        else            asm volatile("cp.async.wait_group 0;" ::: "memory");
        __syncthreads();
        if (c + 2 < c1) issue(c + 2, (st + 2) % NSTAGE);

        const uint32_t abase = sbase + st * STAGE;
        const uint32_t bbase = abase + 32768;
        #pragma unroll
        for (int kk = 0; kk < 4; kk++) {
            const int c16 = kk * 2 + khalf;
            uint32_t afr[4][4], bfr[4][4];
            #pragma unroll
            for (int mt = 0; mt < 4; mt++) {
                const int row = wm * 64 + mt * 16 + t15;
                ldmatrix_x4(afr[mt], abase + row * 128 + ((c16 ^ (row & 7)) << 4));
            }
            #pragma unroll
            for (int nt = 0; nt < 4; nt++) {
                const int row = wn * 64 + nt * 16 + t15;
                ldmatrix_x4(bfr[nt], bbase + row * 128 + ((c16 ^ (row & 7)) << 4));
            }
            #pragma unroll
            for (int mt = 0; mt < 4; mt++) {
                #pragma unroll
                for (int nt = 0; nt < 4; nt++) {
                    mma_16816(acc[mt][nt * 2 + 0], afr[mt], bfr[nt][0], bfr[nt][2]);
                    mma_16816(acc[mt][nt * 2 + 1], afr[mt], bfr[nt][1], bfr[nt][3]);
                }
            }
        }
        __syncthreads();
    }

    float* Cb = (Z == 1) ? g.C : (g.C + (size_t)z * g.partStride);
    #pragma unroll
    for (int mt = 0; mt < 4; mt++) {
        const int row = m0 + wm * 64 + mt * 16 + (lane >> 2);
        #pragma unroll
        for (int nt = 0; nt < 4; nt++) {
            #pragma unroll
            for (int gg = 0; gg < 2; gg++) {
                const int col = n0 + wn * 64 + nt * 16 + gg * 8 + 2 * (lane & 3);
                float* acc4 = acc[mt][nt * 2 + gg];
                float* p0 = Cb + (size_t)row * g.ldc + col;
                float* p1 = p0 + 8 * g.ldc;
                if (Z == 1) {
                    float av0 = 0.f, av1 = 0.f;
                    if (g.addvec) { av0 = g.addvec[col]; av1 = g.addvec[col + 1]; }
                    p0[0] = g.alpha * acc4[0] + av0;
                    p0[1] = g.alpha * acc4[1] + av1;
                    p1[0] = g.alpha * acc4[2] + av0;
                    p1[1] = g.alpha * acc4[3] + av1;
                } else {
                    p0[0] = acc4[0]; p0[1] = acc4[1];
                    p1[0] = acc4[2]; p1[1] = acc4[3];
                }
            }
        }
    }
}

// ======================= fused reductions =======================
// G: sum Z slices over computed lower band, mirror the rest, emit fp16 hi/lo.
__global__ void reduce_mirror_split(const float* __restrict__ part,
                                    __half* __restrict__ hi,
                                    __half* __restrict__ lo, int Z) {
    __shared__ float t[32][33];
    const int C = blockIdx.x * 32, R = blockIdx.y * 32;
    const int X = threadIdx.x, Y = threadIdx.y;
    const bool computed = ((C >> 7) <= 2 * (R >> 8) + 1);
    if (computed) {
        #pragma unroll
        for (int i = 0; i < 32; i += 8) {
            size_t o = (size_t)(R + Y + i) * H + C + X;
            float s = part[o];
            for (int zz = 1; zz < Z; zz++) s += part[o + (size_t)zz * H * H];
            __half h, l; fp16_split(s, h, l);
            hi[o] = h; lo[o] = l;
        }
    } else {
        #pragma unroll
        for (int i = 0; i < 32; i += 8) {
            size_t o = (size_t)(C + Y + i) * H + R + X;   // mirrored source
            float s = part[o];
            for (int zz = 1; zz < Z; zz++) s += part[o + (size_t)zz * H * H];
            t[Y + i][X] = s;
        }
        __syncthreads();
        #pragma unroll
        for (int i = 0; i < 32; i += 8) {
            float v = t[X][Y + i];
            size_t o = (size_t)(R + Y + i) * H + C + X;
            __half h, l; fp16_split(v, h, l);
            hi[o] = h; lo[o] = l;
        }
    }
}

// sum Z slices -> fp16 hi/lo (same layout)
__global__ void reduce_split_n(const float* __restrict__ part,
                               __half* __restrict__ hi,
                               __half* __restrict__ lo, int Z) {
    int i = blockIdx.x * 256 + threadIdx.x;
    float s = part[i];
    for (int zz = 1; zz < Z; zz++) s += part[i + (size_t)zz * H * H];
    __half h, l; fp16_split(s, h, l);
    hi[i] = h; lo[i] = l;
}

// sum Z slices + rank-1 corrections -> fp32 M
__global__ void reduce_rank1(const float* __restrict__ part, float* __restrict__ M,
                             const float* __restrict__ ks, const float* __restrict__ bk,
                             const float* __restrict__ vs, const float* __restrict__ bv,
                             int Z) {
    int idx = blockIdx.x * 256 + threadIdx.x;
    int r = idx >> 10, cc = idx & 1023;
    float s = part[idx];
    for (int zz = 1; zz < Z; zz++) s += part[idx + (size_t)zz * H * H];
    M[idx] = s + ks[r] * bv[cc] + bk[r] * (vs[cc] + 8192.0f * bv[cc]);
}

// sum Z slices, *alpha, emit TRANSPOSED single fp16 (for P -> pt_h)
__global__ void reduce_t_single(const float* __restrict__ part,
                                __half* __restrict__ hi, int Z, float alpha) {
    __shared__ float t[32][33];
    const int C = blockIdx.x * 32, R = blockIdx.y * 32;
    const int X = threadIdx.x, Y = threadIdx.y;
    #pragma unroll
    for (int i = 0; i < 32; i += 8) {
        size_t o = (size_t)(R + Y + i) * H + C + X;
        float s = part[o];
        for (int zz = 1; zz < Z; zz++) s += part[o + (size_t)zz * H * H];
        t[Y + i][X] = alpha * s;
    }
    __syncthreads();
    #pragma unroll
    for (int i = 0; i < 32; i += 8) {
        float v = t[X][Y + i];                         // = P[R+X][C+Y+i]
        size_t o = (size_t)(C + Y + i) * H + R + X;    // pt[c][r]
        hi[o] = __float2half(v);
    }
}

// ======================= split kernels =======================
// one pass over x: emit x_h (fp16 direct) + xt_hi/xt_lo (fp16 transposed)
__global__ void split_x_fused(const float* __restrict__ x,
                              __half* __restrict__ xh,
                              __half* __restrict__ xth, __half* __restrict__ xtl) {
    __shared__ float t[32][33];
    const int bxc = blockIdx.x * 32;   // col base (H dim)
    const int byr = blockIdx.y * 32;   // row base (NROWS dim)
    const int X = threadIdx.x, Y = threadIdx.y;
    #pragma unroll
    for (int i = 0; i < 32; i += 8) {
        size_t o = (size_t)(byr + Y + i) * H + bxc + X;
        float v = x[o];
        t[Y + i][X] = v;
        xh[o] = __float2half(v);
    }
    __syncthreads();
    #pragma unroll
    for (int i = 0; i < 32; i += 8) {
        float v = t[X][Y + i];                              // = x[byr+X][bxc+Y+i]
        size_t o = (size_t)(bxc + Y + i) * NROWS + byr + X; // xt[c][r]
        __half h, l; fp16_split(v, h, l);
        xth[o] = h; xtl[o] = l;
    }
}
__global__ void split_n_kernel(const float* __restrict__ in, __half* __restrict__ hi,
                               __half* __restrict__ lo, int n) {
    int i = blockIdx.x * 256 + threadIdx.x;
    if (i < n) { __half h, l; fp16_split(in[i], h, l); hi[i] = h; lo[i] = l; }
}
__global__ void split_t_kernel(const float* __restrict__ in, __half* __restrict__ hi,
                               __half* __restrict__ lo, int R, int C) {
    __shared__ float t[32][33];
    const int bx = blockIdx.x * 32;
    const int by = blockIdx.y * 32;
    const int x = threadIdx.x, y = threadIdx.y;
    #pragma unroll
    for (int i = 0; i < 32; i += 8)
        t[y + i][x] = in[(size_t)(by + y + i) * C + bx + x];
    __syncthreads();
    #pragma unroll
    for (int i = 0; i < 32; i += 8) {
        float v = t[x][y + i];
        size_t o = (size_t)(bx + y + i) * R + by + x;
        __half h, l; fp16_split(v, h, l);
        hi[o] = h; lo[o] = l;
    }
}

// ======================= small SIMT helpers =======================
__global__ void colsum_part(const float* __restrict__ x, float* __restrict__ part) {
    int j = blockIdx.x * 256 + threadIdx.x;
    int nb = blockIdx.y;
    float s = 0.f;
    int n0 = nb * (NROWS / 32);
    for (int n = n0; n < n0 + (NROWS / 32); n++) s += x[n * H + j];
    part[nb * H + j] = s;
}
__global__ void reduce_part(const float* __restrict__ part, float* __restrict__ out,
                            int cnt, float scale) {
    int j = blockIdx.x * 256 + threadIdx.x;
    float s = 0.f;
    for (int i = 0; i < cnt; i++) s += part[i * H + j];
    out[j] = s * scale;
}
__global__ void matvec_k(const float* __restrict__ W, const float* __restrict__ v,
                         float* __restrict__ out) {
    int row = blockIdx.x * 8 + (threadIdx.x >> 5);
    int lane = threadIdx.x & 31;
    float s = 0.f;
    for (int k = lane; k < H; k += 32) s += W[row * H + k] * v[k];
    #pragma unroll
    for (int o = 16; o > 0; o >>= 1) s += __shfl_xor_sync(0xffffffffu, s, o);
    if (lane == 0) out[row] = s;
}
__global__ void cvec_part(const float* __restrict__ M, const float* __restrict__ b,
                          float* __restrict__ part) {
    int j = blockIdx.x * 256 + threadIdx.x;
    int ib = blockIdx.y;
    float s = 0.f;
    for (int i = ib * 64; i < ib * 64 + 64; i++) s += M[i * H + j] * b[i];
    part[ib * H + j] = s;
}

// ======================= launch =======================
extern "C" void kernel_launch(void* const* d_in, const int* in_sizes, int n_in,
                              void* d_out, int out_size) {
    const float* x  = (const float*)d_in[0];
    const float* Wq = (const float*)d_in[1];
    const float* bq = (const float*)d_in[2];
    const float* Wk = (const float*)d_in[3];
    const float* bk = (const float*)d_in[4];
    const float* Wv = (const float*)d_in[5];
    const float* bv = (const float*)d_in[6];
    float* out = (float*)d_out;

    cudaFuncSetAttribute(mma_gemm, cudaFuncAttributeMaxDynamicSharedMemorySize, GSMEM);

    float *M, *cpart, *spart, *s, *ks, *vs, *c;
    cudaGetSymbolAddress((void**)&M, g_M);
    cudaGetSymbolAddress((void**)&cpart, g_cpart);
    cudaGetSymbolAddress((void**)&spart, g_spart);
    cudaGetSymbolAddress((void**)&s, g_s);
    cudaGetSymbolAddress((void**)&ks, g_ks);
    cudaGetSymbolAddress((void**)&vs, g_vs);
    cudaGetSymbolAddress((void**)&c, g_c);

    __half *xt_hi, *xt_lo, *x_h, *wk_hi, *wk_lo, *wv_hi, *wv_lo;
    __half *wqt_hi, *wqt_lo, *gh, *gl, *th, *tl, *mth, *mtl, *pt_h;
    cudaGetSymbolAddress((void**)&xt_hi, g_xt_hi);
    cudaGetSymbolAddress((void**)&xt_lo, g_xt_lo);
    cudaGetSymbolAddress((void**)&x_h,  g_x_h);
    cudaGetSymbolAddress((void**)&wk_hi, g_wk_hi);
    cudaGetSymbolAddress((void**)&wk_lo, g_wk_lo);
    cudaGetSymbolAddress((void**)&wv_hi, g_wv_hi);
    cudaGetSymbolAddress((void**)&wv_lo, g_wv_lo);
    cudaGetSymbolAddress((void**)&wqt_hi, g_wqt_hi);
    cudaGetSymbolAddress((void**)&wqt_lo, g_wqt_lo);
    cudaGetSymbolAddress((void**)&gh, g_g_hi);
    cudaGetSymbolAddress((void**)&gl, g_g_lo);
    cudaGetSymbolAddress((void**)&th, g_t_hi);
    cudaGetSymbolAddress((void**)&tl, g_t_lo);
    cudaGetSymbolAddress((void**)&mth, g_mt_hi);
    cudaGetSymbolAddress((void**)&mtl, g_mt_lo);
    cudaGetSymbolAddress((void**)&pt_h, g_pt_h);

    const float inv_sqrt_h = 0.03125f;
    const size_t PS = (size_t)H * H;
    dim3 tb(32, 8);

    // ---- splits ----
    split_x_fused<<<dim3(H / 32, NROWS / 32), tb>>>(x, x_h, xt_hi, xt_lo);
    split_n_kernel<<<(H * H) / 256, 256>>>(Wk, wk_hi, wk_lo, H * H);
    split_n_kernel<<<(H * H) / 256, 256>>>(Wv, wv_hi, wv_lo, H * H);
    split_t_kernel<<<dim3(H / 32, H / 32), tb>>>(Wq, wqt_hi, wqt_lo, H, H);

    // ---- s = colsum(x); ks = Wk s; vs = Wv s ----
    colsum_part<<<dim3(4, 32), 256>>>(x, spart);
    reduce_part<<<4, 256>>>(spart, s, 32, 1.0f);
    matvec_k<<<128, 256>>>(Wk, s, ks);
    matvec_k<<<128, 256>>>(Wv, s, vs);

    // ---- G = x^T x : symmetric lower band (20 blocks), 3-term fp16, Z = 8 ----
    {
        GemmArgs a = {xt_hi, xt_hi, xt_lo,  xt_hi, xt_lo, xt_hi,
                      NROWS, NROWS, NROWS, cpart, H, 1.0f, nullptr, PS, 1, 3};
        mma_gemm<<<dim3(20, 1, 8), 256, GSMEM>>>(a);
        reduce_mirror_split<<<dim3(32, 32), tb>>>(cpart, gh, gl, 8);
    }

    // ---- T = Wk @ G  (3-term, Z = 4) ----
    {
        GemmArgs a = {wk_hi, wk_hi, wk_lo,  gh, gl, gh,
                      H, H, H, cpart, H, 1.0f, nullptr, PS, 0, 3};
        mma_gemm<<<dim3(8, 4, 4), 256, GSMEM>>>(a);
        reduce_split_n<<<4096, 256>>>(cpart, th, tl, 4);
    }

    // ---- M = T @ Wv^T + rank-1  (3-term, Z = 4) ----
    {
        GemmArgs a = {th, th, tl,  wv_hi, wv_lo, wv_hi,
                      H, H, H, cpart, H, 1.0f, nullptr, PS, 0, 3};
        mma_gemm<<<dim3(8, 4, 4), 256, GSMEM>>>(a);
        reduce_rank1<<<4096, 256>>>(cpart, M, ks, bk, vs, bv, 4);
    }
    split_t_kernel<<<dim3(H / 32, H / 32), tb>>>(M, mth, mtl, H, H);

    // ---- P = Wq^T @ M / sqrt(H)  (3-term, Z = 4), emitted as transposed fp16 ----
    {
        GemmArgs a = {wqt_hi, wqt_hi, wqt_lo,  mth, mtl, mth,
                      H, H, H, cpart, H, 1.0f, nullptr, PS, 0, 3};
        mma_gemm<<<dim3(8, 4, 4), 256, GSMEM>>>(a);
        reduce_t_single<<<dim3(32, 32), tb>>>(cpart, pt_h, 4, inv_sqrt_h);
    }

    // ---- c = M^T bq / sqrt(H) ----
    cvec_part<<<dim3(4, 16), 256>>>(M, bq, spart);
    reduce_part<<<4, 256>>>(spart, c, 16, inv_sqrt_h);

    // ---- out = x @ P + 1 c^T : SINGLE fp16 term, Z = 1, fused epilogue ----
    {
        GemmArgs a = {x_h, x_h, x_h,  pt_h, pt_h, pt_h,
                      H, H, H, out, H, 1.0f, c, 0, 0, 1};
        mma_gemm<<<dim3(8, NROWS / 256, 1), 256, GSMEM>>>(a);
    }
}

// round 11
// speedup vs baseline: 3.7203x; 1.2295x over previous
#include <cuda_runtime.h>
#include <cuda_fp16.h>
#include <cstdint>
#include <cstddef>

#define NROWS 8192
#define H 1024

// ======================= helpers =======================
__device__ __forceinline__ uint32_t smem_to_u32(const void* p) {
    uint32_t a;
    asm("{ .reg .u64 t; cvta.to.shared.u64 t, %1; cvt.u32.u64 %0, t; }" : "=r"(a) : "l"(p));
    return a;
}
__device__ __forceinline__ void ldmatrix_x4(uint32_t* r, uint32_t addr) {
    asm volatile("ldmatrix.sync.aligned.m8n8.x4.shared.b16 {%0,%1,%2,%3}, [%4];"
                 : "=r"(r[0]), "=r"(r[1]), "=r"(r[2]), "=r"(r[3]) : "r"(addr));
}
__device__ __forceinline__ void mma_16816(float* d, const uint32_t* a, uint32_t b0, uint32_t b1) {
    asm volatile(
        "mma.sync.aligned.m16n8k16.row.col.f32.f16.f16.f32 "
        "{%0,%1,%2,%3}, {%4,%5,%6,%7}, {%8,%9}, {%0,%1,%2,%3};"
        : "+f"(d[0]), "+f"(d[1]), "+f"(d[2]), "+f"(d[3])
        : "r"(a[0]), "r"(a[1]), "r"(a[2]), "r"(a[3]), "r"(b0), "r"(b1));
}
__device__ __forceinline__ void cp_async16(uint32_t saddr, const void* gaddr) {
    asm volatile("cp.async.cg.shared.global [%0], [%1], 16;" :: "r"(saddr), "l"(gaddr));
}
__device__ __forceinline__ void fp16_split(float v, __half& h, __half& l) {
    h = __float2half(v);
    l = __float2half(v - __half2float(h));
}

// ======================= scratch (device globals only) =======================
__device__ __align__(256) float g_cpart[8 * H * H];   // split-K partials
__device__ __align__(256) float g_spart[32 * H];
__device__ float g_s[H];
__device__ float g_ks[H];
__device__ float g_vs[H];
__device__ float g_c[H];

__device__ __align__(256) __half g_xt_hi[H * NROWS];   // x^T fp16 hi/lo
__device__ __align__(256) __half g_xt_lo[H * NROWS];
__device__ __align__(256) __half g_x_h[NROWS * H];     // fp16(x), direct layout
__device__ __align__(256) __half g_wk_hi[H * H], g_wk_lo[H * H];
__device__ __align__(256) __half g_wv_hi[H * H], g_wv_lo[H * H];
__device__ __align__(256) __half g_wqt_hi[H * H], g_wqt_lo[H * H];
__device__ __align__(256) __half g_g_hi[H * H],  g_g_lo[H * H];
__device__ __align__(256) __half g_t_hi[H * H],  g_t_lo[H * H];
__device__ __align__(256) __half g_mt_hi[H * H], g_mt_lo[H * H];
__device__ __align__(256) __half g_pt_h[H * H];        // fp16(P)^T, single term

// ======================= HMMA GEMM: C = alpha * A @ B^T (+ addvec) =======================
// 256x128 CTA tile, 8 warps (4m x 2n), 64x64 warp tile, K-chunk 64, 3-stage cp.async ring.
// nseg segments of Kseg each (total K = nseg*Kseg). Ceil-division split-K over blockIdx.z.
// tri=1: lower-band block decode for symmetric x^T x (grid.x = 20 flattened blocks).
struct GemmArgs {
    const __half* A0; const __half* A1; const __half* A2;
    const __half* B0; const __half* B1; const __half* B2;
    int lda, ldb, Kseg;
    float* C; int ldc;
    float alpha;                 // applied only when Z==1
    const float* addvec;         // only when Z==1; may be null
    size_t partStride;           // slice stride when Z>1
    int tri;
    int nseg;
};

#define STAGE   49152                        // A 32KB + B 16KB
#define NSTAGE  3
#define GSMEM   (NSTAGE * STAGE)             // 147456

__global__ void __launch_bounds__(256, 1) mma_gemm(GemmArgs g) {
    extern __shared__ char smem[];
    const uint32_t sbase = smem_to_u32(smem);
    const int tid = threadIdx.x;
    const int wid = tid >> 5, lane = tid & 31;
    int bx, by;
    if (g.tri) {   // lower-band blocks: cumulative bases {0,2,6,12}
        const int idx = blockIdx.x;
        by = (idx < 2) ? 0 : (idx < 6) ? 1 : (idx < 12) ? 2 : 3;
        bx = idx - by * (by + 1);
    } else { bx = blockIdx.x; by = blockIdx.y; }
    const int m0 = by * 256, n0 = bx * 128;
    const int z = blockIdx.z, Z = gridDim.z;

    const int cps = g.Kseg >> 6;
    const int total = cps * g.nseg;
    const int ncz = (total + Z - 1) / Z;       // ceil
    const int c0 = z * ncz;
    const int c1 = (c0 + ncz < total) ? (c0 + ncz) : total;

    const __half* As[3] = {g.A0, g.A1, g.A2};
    const __half* Bs[3] = {g.B0, g.B1, g.B2};

    const int lrow = tid >> 3;          // 0..31
    const int lc16 = tid & 7;           // 16B column group

    auto issue = [&](int c, int st) {
        const int seg = c / cps;
        const int k0 = (c - seg * cps) << 6;
        const __half* Ap = As[seg] + (size_t)m0 * g.lda + k0;
        const __half* Bp = Bs[seg] + (size_t)n0 * g.ldb + k0;
        const uint32_t abase = sbase + st * STAGE;
        const uint32_t bbase = abase + 32768;
        #pragma unroll
        for (int p = 0; p < 8; p++) {   // A: 256 rows
            const int row = lrow + p * 32;
            const uint32_t so = row * 128 + ((lc16 ^ (row & 7)) << 4);
            cp_async16(abase + so, Ap + (size_t)row * g.lda + lc16 * 8);
        }
        #pragma unroll
        for (int p = 0; p < 4; p++) {   // B: 128 rows
            const int row = lrow + p * 32;
            const uint32_t so = row * 128 + ((lc16 ^ (row & 7)) << 4);
            cp_async16(bbase + so, Bp + (size_t)row * g.ldb + lc16 * 8);
        }
        asm volatile("cp.async.commit_group;" ::: "memory");
    };

    const int wm = wid >> 1;            // 0..3 -> 64 rows
    const int wn = wid & 1;             // 0..1 -> 64 cols
    const int t15 = lane & 15;
    const int khalf = (lane >> 4) & 1;

    float acc[4][8][4];
    #pragma unroll
    for (int i = 0; i < 4; i++)
        #pragma unroll
        for (int j = 0; j < 8; j++)
            #pragma unroll
            for (int q = 0; q < 4; q++) acc[i][j][q] = 0.f;

    if (c0 < c1) {
        issue(c0, 0);
        if (c0 + 1 < c1) issue(c0 + 1, 1);
        for (int c = c0; c < c1; c++) {
            const int st = (c - c0) % NSTAGE;
            if (c + 1 < c1) asm volatile("cp.async.wait_group 1;" ::: "memory");
            else            asm volatile("cp.async.wait_group 0;" ::: "memory");
            __syncthreads();
            if (c + 2 < c1) issue(c + 2, (st + 2) % NSTAGE);

            const uint32_t abase = sbase + st * STAGE;
            const uint32_t bbase = abase + 32768;
            #pragma unroll
            for (int kk = 0; kk < 4; kk++) {
                const int c16 = kk * 2 + khalf;
                uint32_t afr[4][4], bfr[4][4];
                #pragma unroll
                for (int mt = 0; mt < 4; mt++) {
                    const int row = wm * 64 + mt * 16 + t15;
                    ldmatrix_x4(afr[mt], abase + row * 128 + ((c16 ^ (row & 7)) << 4));
                }
                #pragma unroll
                for (int nt = 0; nt < 4; nt++) {
                    const int row = wn * 64 + nt * 16 + t15;
                    ldmatrix_x4(bfr[nt], bbase + row * 128 + ((c16 ^ (row & 7)) << 4));
                }
                #pragma unroll
                for (int mt = 0; mt < 4; mt++) {
                    #pragma unroll
                    for (int nt = 0; nt < 4; nt++) {
                        mma_16816(acc[mt][nt * 2 + 0], afr[mt], bfr[nt][0], bfr[nt][2]);
                        mma_16816(acc[mt][nt * 2 + 1], afr[mt], bfr[nt][1], bfr[nt][3]);
                    }
                }
            }
            __syncthreads();
        }
    }

    float* Cb = (Z == 1) ? g.C : (g.C + (size_t)z * g.partStride);
    #pragma unroll
    for (int mt = 0; mt < 4; mt++) {
        const int row = m0 + wm * 64 + mt * 16 + (lane >> 2);
        #pragma unroll
        for (int nt = 0; nt < 4; nt++) {
            #pragma unroll
            for (int gg = 0; gg < 2; gg++) {
                const int col = n0 + wn * 64 + nt * 16 + gg * 8 + 2 * (lane & 3);
                float* acc4 = acc[mt][nt * 2 + gg];
                float* p0 = Cb + (size_t)row * g.ldc + col;
                float* p1 = p0 + 8 * g.ldc;
                if (Z == 1) {
                    float av0 = 0.f, av1 = 0.f;
                    if (g.addvec) { av0 = g.addvec[col]; av1 = g.addvec[col + 1]; }
                    p0[0] = g.alpha * acc4[0] + av0;
                    p0[1] = g.alpha * acc4[1] + av1;
                    p1[0] = g.alpha * acc4[2] + av0;
                    p1[1] = g.alpha * acc4[3] + av1;
                } else {
                    p0[0] = acc4[0]; p0[1] = acc4[1];
                    p1[0] = acc4[2]; p1[1] = acc4[3];
                }
            }
        }
    }
}

// ======================= fused reductions =======================
// G: sum Z slices over computed lower band, mirror the rest, emit fp16 hi/lo.
__global__ void reduce_mirror_split(const float* __restrict__ part,
                                    __half* __restrict__ hi,
                                    __half* __restrict__ lo, int Z) {
    __shared__ float t[32][33];
    const int C = blockIdx.x * 32, R = blockIdx.y * 32;
    const int X = threadIdx.x, Y = threadIdx.y;
    const bool computed = ((C >> 7) <= 2 * (R >> 8) + 1);
    if (computed) {
        #pragma unroll
        for (int i = 0; i < 32; i += 8) {
            size_t o = (size_t)(R + Y + i) * H + C + X;
            float s = part[o];
            for (int zz = 1; zz < Z; zz++) s += part[o + (size_t)zz * H * H];
            __half h, l; fp16_split(s, h, l);
            hi[o] = h; lo[o] = l;
        }
    } else {
        #pragma unroll
        for (int i = 0; i < 32; i += 8) {
            size_t o = (size_t)(C + Y + i) * H + R + X;   // mirrored source
            float s = part[o];
            for (int zz = 1; zz < Z; zz++) s += part[o + (size_t)zz * H * H];
            t[Y + i][X] = s;
        }
        __syncthreads();
        #pragma unroll
        for (int i = 0; i < 32; i += 8) {
            float v = t[X][Y + i];
            size_t o = (size_t)(R + Y + i) * H + C + X;
            __half h, l; fp16_split(v, h, l);
            hi[o] = h; lo[o] = l;
        }
    }
}

// sum Z slices -> fp16 hi/lo (same layout)
__global__ void reduce_split_n(const float* __restrict__ part,
                               __half* __restrict__ hi,
                               __half* __restrict__ lo, int Z) {
    int i = blockIdx.x * 256 + threadIdx.x;
    float s = part[i];
    for (int zz = 1; zz < Z; zz++) s += part[i + (size_t)zz * H * H];
    __half h, l; fp16_split(s, h, l);
    hi[i] = h; lo[i] = l;
}

// sum Z slices + rank-1 corrections, emit TRANSPOSED fp16 hi/lo (M never hits fp32 gmem)
__global__ void reduce_rank1_t(const float* __restrict__ part,
                               __half* __restrict__ hi, __half* __restrict__ lo,
                               const float* __restrict__ ks, const float* __restrict__ bk,
                               const float* __restrict__ vs, const float* __restrict__ bv,
                               int Z) {
    __shared__ float t[32][33];
    const int C = blockIdx.x * 32, R = blockIdx.y * 32;
    const int X = threadIdx.x, Y = threadIdx.y;
    #pragma unroll
    for (int i = 0; i < 32; i += 8) {
        const int r = R + Y + i, cc = C + X;
        size_t o = (size_t)r * H + cc;
        float s = part[o];
        for (int zz = 1; zz < Z; zz++) s += part[o + (size_t)zz * H * H];
        s += ks[r] * bv[cc] + bk[r] * (vs[cc] + 8192.0f * bv[cc]);
        t[Y + i][X] = s;
    }
    __syncthreads();
    #pragma unroll
    for (int i = 0; i < 32; i += 8) {
        float v = t[X][Y + i];                         // = M[R+X][C+Y+i]
        size_t o = (size_t)(C + Y + i) * H + R + X;    // mt[c][r]
        __half h, l; fp16_split(v, h, l);
        hi[o] = h; lo[o] = l;
    }
}

// sum Z slices, *alpha, emit TRANSPOSED single fp16 (for P -> pt_h)
__global__ void reduce_t_single(const float* __restrict__ part,
                                __half* __restrict__ hi, int Z, float alpha) {
    __shared__ float t[32][33];
    const int C = blockIdx.x * 32, R = blockIdx.y * 32;
    const int X = threadIdx.x, Y = threadIdx.y;
    #pragma unroll
    for (int i = 0; i < 32; i += 8) {
        size_t o = (size_t)(R + Y + i) * H + C + X;
        float s = part[o];
        for (int zz = 1; zz < Z; zz++) s += part[o + (size_t)zz * H * H];
        t[Y + i][X] = alpha * s;
    }
    __syncthreads();
    #pragma unroll
    for (int i = 0; i < 32; i += 8) {
        float v = t[X][Y + i];
        size_t o = (size_t)(C + Y + i) * H + R + X;
        hi[o] = __float2half(v);
    }
}

// ======================= split kernels =======================
__global__ void split_x_fused(const float* __restrict__ x,
                              __half* __restrict__ xh,
                              __half* __restrict__ xth, __half* __restrict__ xtl) {
    __shared__ float t[32][33];
    const int bxc = blockIdx.x * 32;
    const int byr = blockIdx.y * 32;
    const int X = threadIdx.x, Y = threadIdx.y;
    #pragma unroll
    for (int i = 0; i < 32; i += 8) {
        size_t o = (size_t)(byr + Y + i) * H + bxc + X;
        float v = x[o];
        t[Y + i][X] = v;
        xh[o] = __float2half(v);
    }
    __syncthreads();
    #pragma unroll
    for (int i = 0; i < 32; i += 8) {
        float v = t[X][Y + i];
        size_t o = (size_t)(bxc + Y + i) * NROWS + byr + X;
        __half h, l; fp16_split(v, h, l);
        xth[o] = h; xtl[o] = l;
    }
}
__global__ void split_n_kernel(const float* __restrict__ in, __half* __restrict__ hi,
                               __half* __restrict__ lo, int n) {
    int i = blockIdx.x * 256 + threadIdx.x;
    if (i < n) { __half h, l; fp16_split(in[i], h, l); hi[i] = h; lo[i] = l; }
}
__global__ void split_t_kernel(const float* __restrict__ in, __half* __restrict__ hi,
                               __half* __restrict__ lo, int R, int C) {
    __shared__ float t[32][33];
    const int bx = blockIdx.x * 32;
    const int by = blockIdx.y * 32;
    const int x = threadIdx.x, y = threadIdx.y;
    #pragma unroll
    for (int i = 0; i < 32; i += 8)
        t[y + i][x] = in[(size_t)(by + y + i) * C + bx + x];
    __syncthreads();
    #pragma unroll
    for (int i = 0; i < 32; i += 8) {
        float v = t[x][y + i];
        size_t o = (size_t)(bx + y + i) * R + by + x;
        __half h, l; fp16_split(v, h, l);
        hi[o] = h; lo[o] = l;
    }
}

// ======================= small SIMT helpers =======================
__global__ void colsum_part(const float* __restrict__ x, float* __restrict__ part) {
    int j = blockIdx.x * 256 + threadIdx.x;
    int nb = blockIdx.y;
    float s = 0.f;
    int n0 = nb * (NROWS / 32);
    for (int n = n0; n < n0 + (NROWS / 32); n++) s += x[n * H + j];
    part[nb * H + j] = s;
}
__global__ void reduce_part(const float* __restrict__ part, float* __restrict__ out,
                            int cnt, float scale) {
    int j = blockIdx.x * 256 + threadIdx.x;
    float s = 0.f;
    for (int i = 0; i < cnt; i++) s += part[i * H + j];
    out[j] = s * scale;
}
__global__ void matvec_k(const float* __restrict__ W, const float* __restrict__ v,
                         float* __restrict__ out) {
    int row = blockIdx.x * 8 + (threadIdx.x >> 5);
    int lane = threadIdx.x & 31;
    float s = 0.f;
    for (int k = lane; k < H; k += 32) s += W[row * H + k] * v[k];
    #pragma unroll
    for (int o = 16; o > 0; o >>= 1) s += __shfl_xor_sync(0xffffffffu, s, o);
    if (lane == 0) out[row] = s;
}
// c_j = scale * sum_i (mth[j][i] + mtl[j][i]) * bq[i]     (mt[j][i] = M[i][j])
__global__ void matvec_c(const __half* __restrict__ mth, const __half* __restrict__ mtl,
                         const float* __restrict__ bq, float* __restrict__ out, float scale) {
    int row = blockIdx.x * 8 + (threadIdx.x >> 5);
    int lane = threadIdx.x & 31;
    float s = 0.f;
    for (int k = lane; k < H; k += 32) {
        size_t o = (size_t)row * H + k;
        s += (__half2float(mth[o]) + __half2float(mtl[o])) * bq[k];
    }
    #pragma unroll
    for (int o = 16; o > 0; o >>= 1) s += __shfl_xor_sync(0xffffffffu, s, o);
    if (lane == 0) out[row] = s * scale;
}

// ======================= launch =======================
extern "C" void kernel_launch(void* const* d_in, const int* in_sizes, int n_in,
                              void* d_out, int out_size) {
    const float* x  = (const float*)d_in[0];
    const float* Wq = (const float*)d_in[1];
    const float* bq = (const float*)d_in[2];
    const float* Wk = (const float*)d_in[3];
    const float* bk = (const float*)d_in[4];
    const float* Wv = (const float*)d_in[5];
    const float* bv = (const float*)d_in[6];
    float* out = (float*)d_out;

    cudaFuncSetAttribute(mma_gemm, cudaFuncAttributeMaxDynamicSharedMemorySize, GSMEM);

    float *cpart, *spart, *s, *ks, *vs, *c;
    cudaGetSymbolAddress((void**)&cpart, g_cpart);
    cudaGetSymbolAddress((void**)&spart, g_spart);
    cudaGetSymbolAddress((void**)&s, g_s);
    cudaGetSymbolAddress((void**)&ks, g_ks);
    cudaGetSymbolAddress((void**)&vs, g_vs);
    cudaGetSymbolAddress((void**)&c, g_c);

    __half *xt_hi, *xt_lo, *x_h, *wk_hi, *wk_lo, *wv_hi, *wv_lo;
    __half *wqt_hi, *wqt_lo, *gh, *gl, *th, *tl, *mth, *mtl, *pt_h;
    cudaGetSymbolAddress((void**)&xt_hi, g_xt_hi);
    cudaGetSymbolAddress((void**)&xt_lo, g_xt_lo);
    cudaGetSymbolAddress((void**)&x_h,  g_x_h);
    cudaGetSymbolAddress((void**)&wk_hi, g_wk_hi);
    cudaGetSymbolAddress((void**)&wk_lo, g_wk_lo);
    cudaGetSymbolAddress((void**)&wv_hi, g_wv_hi);
    cudaGetSymbolAddress((void**)&wv_lo, g_wv_lo);
    cudaGetSymbolAddress((void**)&wqt_hi, g_wqt_hi);
    cudaGetSymbolAddress((void**)&wqt_lo, g_wqt_lo);
    cudaGetSymbolAddress((void**)&gh, g_g_hi);
    cudaGetSymbolAddress((void**)&gl, g_g_lo);
    cudaGetSymbolAddress((void**)&th, g_t_hi);
    cudaGetSymbolAddress((void**)&tl, g_t_lo);
    cudaGetSymbolAddress((void**)&mth, g_mt_hi);
    cudaGetSymbolAddress((void**)&mtl, g_mt_lo);
    cudaGetSymbolAddress((void**)&pt_h, g_pt_h);

    const float inv_sqrt_h = 0.03125f;
    const size_t PS = (size_t)H * H;
    dim3 tb(32, 8);

    // ---- splits ----
    split_x_fused<<<dim3(H / 32, NROWS / 32), tb>>>(x, x_h, xt_hi, xt_lo);
    split_n_kernel<<<(H * H) / 256, 256>>>(Wk, wk_hi, wk_lo, H * H);
    split_n_kernel<<<(H * H) / 256, 256>>>(Wv, wv_hi, wv_lo, H * H);
    split_t_kernel<<<dim3(H / 32, H / 32), tb>>>(Wq, wqt_hi, wqt_lo, H, H);

    // ---- s = colsum(x); ks = Wk s; vs = Wv s ----
    colsum_part<<<dim3(4, 32), 256>>>(x, spart);
    reduce_part<<<4, 256>>>(spart, s, 32, 1.0f);
    matvec_k<<<128, 256>>>(Wk, s, ks);
    matvec_k<<<128, 256>>>(Wv, s, vs);

    // ---- G = x^T x : symmetric lower band (20 blocks), 3-term fp16, Z = 7 (140 CTAs, 1 wave) ----
    {
        GemmArgs a = {xt_hi, xt_hi, xt_lo,  xt_hi, xt_lo, xt_hi,
                      NROWS, NROWS, NROWS, cpart, H, 1.0f, nullptr, PS, 1, 3};
        mma_gemm<<<dim3(20, 1, 7), 256, GSMEM>>>(a);
        reduce_mirror_split<<<dim3(32, 32), tb>>>(cpart, gh, gl, 7);
    }

    // ---- T = Wk @ G  (3-term, Z = 4) ----
    {
        GemmArgs a = {wk_hi, wk_hi, wk_lo,  gh, gl, gh,
                      H, H, H, cpart, H, 1.0f, nullptr, PS, 0, 3};
        mma_gemm<<<dim3(8, 4, 4), 256, GSMEM>>>(a);
        reduce_split_n<<<4096, 256>>>(cpart, th, tl, 4);
    }

    // ---- M = T @ Wv^T + rank-1, emitted directly as transposed fp16 split  (Z = 4) ----
    {
        GemmArgs a = {th, th, tl,  wv_hi, wv_lo, wv_hi,
                      H, H, H, cpart, H, 1.0f, nullptr, PS, 0, 3};
        mma_gemm<<<dim3(8, 4, 4), 256, GSMEM>>>(a);
        reduce_rank1_t<<<dim3(32, 32), tb>>>(cpart, mth, mtl, ks, bk, vs, bv, 4);
    }

    // ---- c = M^T bq / sqrt(H)  (from fp16 pair) ----
    matvec_c<<<128, 256>>>(mth, mtl, bq, c, inv_sqrt_h);

    // ---- P = Wq^T @ M / sqrt(H)  (3-term, Z = 4), emitted as transposed fp16 ----
    {
        GemmArgs a = {wqt_hi, wqt_hi, wqt_lo,  mth, mtl, mth,
                      H, H, H, cpart, H, 1.0f, nullptr, PS, 0, 3};
        mma_gemm<<<dim3(8, 4, 4), 256, GSMEM>>>(a);
        reduce_t_single<<<dim3(32, 32), tb>>>(cpart, pt_h, 4, inv_sqrt_h);
    }

    // ---- out = x @ P + 1 c^T : SINGLE fp16 term, Z = 1, fused epilogue ----
    {
        GemmArgs a = {x_h, x_h, x_h,  pt_h, pt_h, pt_h,
                      H, H, H, out, H, 1.0f, c, 0, 0, 1};
        mma_gemm<<<dim3(8, NROWS / 256, 1), 256, GSMEM>>>(a);
    }
}